// round 12
// baseline (speedup 1.0000x reference)
#include <cuda_runtime.h>
#include <cuda_bf16.h>
#include <math.h>
#include <stdint.h>

#define B_   4
#define C_   256
#define CI_  128
#define HW_  4096
#define MALL (B_*HW_)          // 16384
#define EPSbn 1e-5f

// ---------------- static scratch (no allocations allowed) ----------------
__device__ __nv_bfloat16 g_th[(size_t)MALL * CI_];      // theta hi [m][ci]
__device__ __nv_bfloat16 g_tl[(size_t)MALL * CI_];      // theta lo
__device__ __nv_bfloat16 g_phh[(size_t)MALL * CI_];     // phi hi
__device__ __nv_bfloat16 g_phl[(size_t)MALL * CI_];     // phi lo
__device__ __nv_bfloat16 g_gh[(size_t)MALL * CI_];      // g hi [m][ci]
__device__ __nv_bfloat16 g_gl[(size_t)MALL * CI_];      // g lo
__device__ __nv_bfloat16 g_yh[(size_t)MALL * CI_];      // y hi
__device__ __nv_bfloat16 g_yl[(size_t)MALL * CI_];      // y lo
__device__ __nv_bfloat16 g_owh[(size_t)C_ * CI_];       // out_w hi
__device__ __nv_bfloat16 g_owl[(size_t)C_ * CI_];       // out_w lo
__device__ float g_o[(size_t)MALL * C_];
__device__ float g_ps[2][128][256];                     // per-128-row-chunk stats
__device__ float g_scale[C_];
__device__ float g_shift[C_];

// ---------------- portable tensor-core helpers (sm_80+ PTX) ---------------
__device__ __forceinline__ uint32_t smem_u32(const void* p) {
    uint32_t a;
    asm("{ .reg .u64 t; cvta.to.shared.u64 t, %1; cvt.u32.u64 %0, t; }" : "=r"(a) : "l"(p));
    return a;
}
__device__ __forceinline__ void ldsm4(uint32_t* r, uint32_t addr) {
    asm volatile("ldmatrix.sync.aligned.m8n8.x4.shared.b16 {%0,%1,%2,%3}, [%4];"
        : "=r"(r[0]), "=r"(r[1]), "=r"(r[2]), "=r"(r[3]) : "r"(addr));
}
__device__ __forceinline__ void ldsm4t(uint32_t* r, uint32_t addr) {
    asm volatile("ldmatrix.sync.aligned.m8n8.x4.trans.shared.b16 {%0,%1,%2,%3}, [%4];"
        : "=r"(r[0]), "=r"(r[1]), "=r"(r[2]), "=r"(r[3]) : "r"(addr));
}
__device__ __forceinline__ void mma_bf16(float* c, const uint32_t* a, const uint32_t* b) {
    asm volatile(
        "mma.sync.aligned.m16n8k16.row.col.f32.bf16.bf16.f32 "
        "{%0,%1,%2,%3}, {%4,%5,%6,%7}, {%8,%9}, {%0,%1,%2,%3};"
        : "+f"(c[0]), "+f"(c[1]), "+f"(c[2]), "+f"(c[3])
        : "r"(a[0]), "r"(a[1]), "r"(a[2]), "r"(a[3]), "r"(b[0]), "r"(b[1]));
}
__device__ __forceinline__ void split1(float v, __nv_bfloat16& h, __nv_bfloat16& l) {
    h = __float2bfloat16(v);
    l = __float2bfloat16(v - __bfloat162float(h));
}
__device__ __forceinline__ uint32_t pack2(__nv_bfloat16 a, __nv_bfloat16 b) {
    __nv_bfloat162 v; v.x = a; v.y = b;
    return *(uint32_t*)&v;
}
__device__ __forceinline__ void cpa16(uint32_t dst, const void* src) {
    asm volatile("cp.async.cg.shared.global [%0], [%1], 16;" :: "r"(dst), "l"(src));
}
#define CP_COMMIT() asm volatile("cp.async.commit_group;" ::: "memory")
#define CP_WAIT0()  asm volatile("cp.async.wait_group 0;" ::: "memory")
// PDL: signal downstream PDL-launched kernels that they may begin
#define GDC_TRIGGER() asm volatile("griddepcontrol.launch_dependents;" ::: "memory")

// ---------------- kernel 1: projections -> bf16 hi/lo planes [m][ci] ------
// per-batch launch: grid (6 n-tiles, 64 m-tiles), param b
__global__ void proj_kernel(const float* __restrict__ x,
                            const float* __restrict__ gw,  const float* __restrict__ gb,
                            const float* __restrict__ tw,  const float* __restrict__ tb,
                            const float* __restrict__ pw,  const float* __restrict__ pb,
                            int b) {
    __shared__ float As[16][68];
    __shared__ float Bs[16][68];
    const int tid = threadIdx.x;
    const int n0 = blockIdx.x * 64;            // 0..383
    const int s0 = blockIdx.y * 64;
    const int m0 = b * HW_ + s0;

    const float* wbase; const float* bbase; int j0;
    if      (n0 < 128) { wbase = gw; bbase = gb; j0 = n0;       }
    else if (n0 < 256) { wbase = tw; bbase = tb; j0 = n0 - 128; }
    else               { wbase = pw; bbase = pb; j0 = n0 - 256; }
    const int seg = n0 >> 7;

    const float* xb = x + (size_t)b * C_ * HW_;
    const int tx = tid & 15, ty = tid >> 4;
    float acc[4][4] = {};

    const int la_kk = tid >> 4, la_m4 = (tid & 15) * 4;
    const int lb_nn = tid >> 2, lb_k4 = (tid & 3) * 4;

    for (int k0 = 0; k0 < C_; k0 += 16) {
        float4 av = *(const float4*)&xb[(k0 + la_kk) * HW_ + s0 + la_m4];
        As[la_kk][la_m4+0] = av.x; As[la_kk][la_m4+1] = av.y;
        As[la_kk][la_m4+2] = av.z; As[la_kk][la_m4+3] = av.w;
        float4 bv = *(const float4*)&wbase[(j0 + lb_nn) * C_ + k0 + lb_k4];
        Bs[lb_k4+0][lb_nn] = bv.x; Bs[lb_k4+1][lb_nn] = bv.y;
        Bs[lb_k4+2][lb_nn] = bv.z; Bs[lb_k4+3][lb_nn] = bv.w;
        __syncthreads();
        #pragma unroll
        for (int kk = 0; kk < 16; kk++) {
            float a[4], bb[4];
            #pragma unroll
            for (int i = 0; i < 4; i++) a[i]  = As[kk][ty*4 + i];
            #pragma unroll
            for (int j = 0; j < 4; j++) bb[j] = Bs[kk][tx*4 + j];
            #pragma unroll
            for (int i = 0; i < 4; i++)
                #pragma unroll
                for (int j = 0; j < 4; j++) acc[i][j] += a[i] * bb[j];
        }
        __syncthreads();
    }

    __nv_bfloat16* ph = (seg == 0) ? g_gh : ((seg == 1) ? g_th : g_phh);
    __nv_bfloat16* pl = (seg == 0) ? g_gl : ((seg == 1) ? g_tl : g_phl);
    #pragma unroll
    for (int i = 0; i < 4; i++) {
        const int m = m0 + ty*4 + i;
        const int j = j0 + tx*4;
        union { __nv_bfloat16 h[4]; uint2 u; } H;
        union { __nv_bfloat16 l[4]; uint2 u; } L;
        #pragma unroll
        for (int jj = 0; jj < 4; jj++)
            split1(acc[i][jj] + bbase[j+jj], H.h[jj], L.l[jj]);
        *(uint2*)&ph[(size_t)m * CI_ + j] = H.u;
        *(uint2*)&pl[(size_t)m * CI_ + j] = L.u;
    }
}

// ---------------- kernel 1b: out_w -> bf16 hi/lo --------------------------
__global__ void wconv_kernel(const float* __restrict__ ow) {
    const int i = blockIdx.x * 256 + threadIdx.x;   // 0..32767
    split1(ow[i], g_owh[i], g_owl[i]);
}

// ---------------- kernel 2: fused flash attention, 4 warps, 2 CTA/SM ------
// per-batch launch: grid (64 m-tiles), param b
#define ATT_SMEM 104448
__global__ __launch_bounds__(128, 2) void attn_fused(int b) {
    extern __shared__ char sm[];
    // release downstream PDL kernels (next batch's projection) immediately
    GDC_TRIGGER();
    const int t = threadIdx.x, w = t >> 5, l = t & 31;
    const int m0 = blockIdx.x * 64;

    char* TH = sm;
    char* TL = sm + 17408;

    const size_t thbase = ((size_t)b * HW_ + m0) * CI_;
    const __nv_bfloat16* PhiH = g_phh + (size_t)b * HW_ * CI_;
    const __nv_bfloat16* PhiL = g_phl + (size_t)b * HW_ * CI_;
    const __nv_bfloat16* GHp  = g_gh  + (size_t)b * HW_ * CI_;
    const __nv_bfloat16* GLp  = g_gl  + (size_t)b * HW_ * CI_;

    for (int i = t; i < 1024; i += 128) {
        const int row = i >> 4, c16 = i & 15;
        cpa16(smem_u32(TH + row*272 + c16*16), g_th + thbase + (size_t)row*CI_ + c16*8);
        cpa16(smem_u32(TL + row*272 + c16*16), g_tl + thbase + (size_t)row*CI_ + c16*8);
    }

    auto load_chunk = [&](int buf, int n0) {
        char* base = sm + 34816 + buf * 34816;
        for (int i = t; i < 512; i += 128) {
            const int row = i >> 4, c16 = i & 15;
            const size_t so = (size_t)(n0 + row) * CI_ + c16 * 8;
            const int dof = row*272 + c16*16;
            cpa16(smem_u32(base +         dof), PhiH + so);
            cpa16(smem_u32(base +  8704 + dof), PhiL + so);
            cpa16(smem_u32(base + 17408 + dof), GHp + so);
            cpa16(smem_u32(base + 26112 + dof), GLp + so);
        }
    };

    load_chunk(0, 0);
    CP_COMMIT();

    const int wm = w * 16;

    const int a_row = (l & 7) + ((l >> 3) & 1) * 8;
    const int a_kb  = (l >> 4) * 8;
    const int b_row = (l & 7) + (l >> 4) * 8;
    const int b_kb  = ((l >> 3) & 1) * 8;
    const int y_row = (l & 7) + ((l >> 3) & 1) * 8;
    const int y_cb  = (l >> 4) * 8;
    const int qr = l >> 2, qc = (l & 3) * 2;

    float Y[16][4];
    #pragma unroll
    for (int i = 0; i < 16; i++)
        #pragma unroll
        for (int j = 0; j < 4; j++) Y[i][j] = 0.f;
    float rs0 = 0.f, rs1 = 0.f;

    for (int c = 0; c < 128; c++) {
        const int cur = c & 1;
        CP_WAIT0();
        __syncthreads();
        if (c + 1 < 128) { load_chunk(cur ^ 1, (c + 1) * 32); CP_COMMIT(); }

        char* FH = sm + 34816 + cur * 34816;
        char* FL = FH + 8704;
        char* GS = FH + 17408;
        char* GSL = FH + 26112;

        // ---- S = theta . phi^T (16 rows x 32 keys, K=128, bf16x3) ----
        float S[4][4];
        #pragma unroll
        for (int i = 0; i < 4; i++)
            #pragma unroll
            for (int j = 0; j < 4; j++) S[i][j] = 0.f;

        #pragma unroll
        for (int ks = 0; ks < 8; ks++) {
            uint32_t aH[4], aL[4];
            const int aoff = (wm + a_row) * 272 + (ks*16 + a_kb) * 2;
            ldsm4(aH, smem_u32(TH + aoff));
            ldsm4(aL, smem_u32(TL + aoff));
            uint32_t bH[4][2], bL[4][2];
            #pragma unroll
            for (int q = 0; q < 2; q++) {
                const int boff = (q*16 + b_row) * 272 + (ks*16 + b_kb) * 2;
                uint32_t r[4];
                ldsm4(r, smem_u32(FH + boff));
                bH[2*q][0] = r[0]; bH[2*q][1] = r[1];
                bH[2*q+1][0] = r[2]; bH[2*q+1][1] = r[3];
                ldsm4(r, smem_u32(FL + boff));
                bL[2*q][0] = r[0]; bL[2*q][1] = r[1];
                bL[2*q+1][0] = r[2]; bL[2*q+1][1] = r[3];
            }
            #pragma unroll
            for (int nf = 0; nf < 4; nf++) {
                mma_bf16(S[nf], aH, bH[nf]);
                mma_bf16(S[nf], aH, bL[nf]);
                mma_bf16(S[nf], aL, bH[nf]);
            }
        }

        // ---- exp(s-20) in regs + rowsum ----
        #pragma unroll
        for (int nf = 0; nf < 4; nf++) {
            S[nf][0] = __expf(S[nf][0] - 20.0f);
            S[nf][1] = __expf(S[nf][1] - 20.0f);
            S[nf][2] = __expf(S[nf][2] - 20.0f);
            S[nf][3] = __expf(S[nf][3] - 20.0f);
            rs0 += S[nf][0] + S[nf][1];
            rs1 += S[nf][2] + S[nf][3];
        }

        // ---- Y += P . g  (K = 32 keys, A-frags from C-frags; trans B) ----
        #pragma unroll
        for (int ks = 0; ks < 2; ks++) {
            uint32_t aH[4], aL[4];
            {
                __nv_bfloat16 h0,l0,h1,l1;
                const float* s0 = S[2*ks];
                const float* s1 = S[2*ks+1];
                split1(s0[0], h0, l0); split1(s0[1], h1, l1);
                aH[0] = pack2(h0, h1); aL[0] = pack2(l0, l1);
                split1(s0[2], h0, l0); split1(s0[3], h1, l1);
                aH[1] = pack2(h0, h1); aL[1] = pack2(l0, l1);
                split1(s1[0], h0, l0); split1(s1[1], h1, l1);
                aH[2] = pack2(h0, h1); aL[2] = pack2(l0, l1);
                split1(s1[2], h0, l0); split1(s1[3], h1, l1);
                aH[3] = pack2(h0, h1); aL[3] = pack2(l0, l1);
            }
            #pragma unroll
            for (int q = 0; q < 8; q++) {
                const int boff = (ks*16 + y_row) * 272 + (q*16 + y_cb) * 2;
                uint32_t rh[4], rl[4];
                ldsm4t(rh, smem_u32(GS + boff));
                ldsm4t(rl, smem_u32(GSL + boff));
                uint32_t bh0[2] = {rh[0], rh[1]}, bh1[2] = {rh[2], rh[3]};
                uint32_t bl0[2] = {rl[0], rl[1]}, bl1[2] = {rl[2], rl[3]};
                mma_bf16(Y[2*q],   aH, bh0);
                mma_bf16(Y[2*q],   aH, bl0);
                mma_bf16(Y[2*q],   aL, bh0);
                mma_bf16(Y[2*q+1], aH, bh1);
                mma_bf16(Y[2*q+1], aH, bl1);
                mma_bf16(Y[2*q+1], aL, bh1);
            }
        }
    }

    // ---- epilogue: quad rowsum reduce, normalize, bf16 hi/lo y ----
    rs0 += __shfl_xor_sync(0xffffffffu, rs0, 1);
    rs0 += __shfl_xor_sync(0xffffffffu, rs0, 2);
    rs1 += __shfl_xor_sync(0xffffffffu, rs1, 1);
    rs1 += __shfl_xor_sync(0xffffffffu, rs1, 2);
    const float ri0 = 1.0f / rs0;
    const float ri1 = 1.0f / rs1;

    const size_t yb = (size_t)b * HW_ + m0;
    const int r0 = wm + qr, r1 = r0 + 8;
    #pragma unroll
    for (int nf = 0; nf < 16; nf++) {
        const int col = nf*8 + qc;
        float v00 = Y[nf][0] * ri0, v01 = Y[nf][1] * ri0;
        float v10 = Y[nf][2] * ri1, v11 = Y[nf][3] * ri1;
        __nv_bfloat16 h0,l0,h1,l1;
        split1(v00, h0, l0); split1(v01, h1, l1);
        *(uint32_t*)&g_yh[(yb + r0) * CI_ + col] = pack2(h0, h1);
        *(uint32_t*)&g_yl[(yb + r0) * CI_ + col] = pack2(l0, l1);
        split1(v10, h0, l0); split1(v11, h1, l1);
        *(uint32_t*)&g_yh[(yb + r1) * CI_ + col] = pack2(h0, h1);
        *(uint32_t*)&g_yl[(yb + r1) * CI_ + col] = pack2(l0, l1);
    }
}

// ---------------- kernel 3: out conv via mma + fused BN partial stats -----
#define OC_PITCH 272
#define OC_PLANE (128 * OC_PITCH)   // 34816
__global__ __launch_bounds__(256, 1) void outconv_mma(const float* __restrict__ bias) {
    extern __shared__ char dsm[];
    const int t  = threadIdx.x;
    const int w  = t >> 5;
    const int l  = t & 31;
    const int m0 = blockIdx.y * 128;
    const int n0 = blockIdx.x * 128;

    char* Ah = dsm;
    char* Al = dsm + OC_PLANE;
    char* Bh = dsm + 2 * OC_PLANE;
    char* Bl = dsm + 3 * OC_PLANE;

    {
        const size_t ar = (size_t)m0 * CI_;
        const size_t br = (size_t)n0 * CI_;
        for (int i = t; i < 2048; i += 256) {
            const int row = i >> 4, c = i & 15;
            const size_t so = (size_t)row * CI_ + c * 8;
            const int dof = row * OC_PITCH + c * 16;
            cpa16(smem_u32(Ah + dof), g_yh  + ar + so);
            cpa16(smem_u32(Al + dof), g_yl  + ar + so);
            cpa16(smem_u32(Bh + dof), g_owh + br + so);
            cpa16(smem_u32(Bl + dof), g_owl + br + so);
        }
    }
    CP_COMMIT(); CP_WAIT0();
    __syncthreads();

    const int wm = (w >> 1) * 32;
    const int wn = (w & 1) * 64;

    float acc[2][8][4];
    #pragma unroll
    for (int i = 0; i < 2; i++)
        #pragma unroll
        for (int j = 0; j < 8; j++)
            #pragma unroll
            for (int k = 0; k < 4; k++) acc[i][j][k] = 0.f;

    const int a_row = (l & 7) + ((l >> 3) & 1) * 8;
    const int a_kb  = (l >> 4) * 8;
    const int b_row = (l & 7) + (l >> 4) * 8;
    const int b_kb  = ((l >> 3) & 1) * 8;

    #pragma unroll
    for (int ks = 0; ks < 8; ks++) {
        uint32_t aH[2][4], aL[2][4];
        #pragma unroll
        for (int mf = 0; mf < 2; mf++) {
            const int off = (wm + mf*16 + a_row) * OC_PITCH + (ks*16 + a_kb) * 2;
            ldsm4(aH[mf], smem_u32(Ah + off));
            ldsm4(aL[mf], smem_u32(Al + off));
        }
        uint32_t bH[8][2], bL[8][2];
        #pragma unroll
        for (int q = 0; q < 4; q++) {
            const int off = (wn + q*16 + b_row) * OC_PITCH + (ks*16 + b_kb) * 2;
            uint32_t r[4];
            ldsm4(r, smem_u32(Bh + off));
            bH[2*q][0] = r[0]; bH[2*q][1] = r[1]; bH[2*q+1][0] = r[2]; bH[2*q+1][1] = r[3];
            ldsm4(r, smem_u32(Bl + off));
            bL[2*q][0] = r[0]; bL[2*q][1] = r[1]; bL[2*q+1][0] = r[2]; bL[2*q+1][1] = r[3];
        }
        #pragma unroll
        for (int mf = 0; mf < 2; mf++)
            #pragma unroll
            for (int nf = 0; nf < 8; nf++) {
                mma_bf16(acc[mf][nf], aH[mf], bH[nf]);
                mma_bf16(acc[mf][nf], aH[mf], bL[nf]);
                mma_bf16(acc[mf][nf], aL[mf], bH[nf]);
            }
    }

    // add bias, store o, accumulate per-col partial sums/sumsq
    const int qr = l >> 2, qc = (l & 3) * 2;
    float cs[16], cq[16];
    #pragma unroll
    for (int i = 0; i < 16; i++) { cs[i] = 0.f; cq[i] = 0.f; }

    #pragma unroll
    for (int mf = 0; mf < 2; mf++) {
        const int r0 = m0 + wm + mf*16 + qr;
        const int r1 = r0 + 8;
        #pragma unroll
        for (int nf = 0; nf < 8; nf++) {
            const int col = n0 + wn + nf*8 + qc;
            const float b0 = bias[col], b1 = bias[col+1];
            float v0 = acc[mf][nf][0] + b0, v1 = acc[mf][nf][1] + b1;
            float v2 = acc[mf][nf][2] + b0, v3 = acc[mf][nf][3] + b1;
            *(float2*)&g_o[(size_t)r0 * C_ + col] = make_float2(v0, v1);
            *(float2*)&g_o[(size_t)r1 * C_ + col] = make_float2(v2, v3);
            cs[2*nf]   += v0 + v2;  cq[2*nf]   += v0*v0 + v2*v2;
            cs[2*nf+1] += v1 + v3;  cq[2*nf+1] += v1*v1 + v3*v3;
        }
    }
    #pragma unroll
    for (int i = 0; i < 16; i++) {
        #pragma unroll
        for (int o = 4; o < 32; o <<= 1) {
            cs[i] += __shfl_xor_sync(0xffffffffu, cs[i], o);
            cq[i] += __shfl_xor_sync(0xffffffffu, cq[i], o);
        }
    }
    __syncthreads();
    float* red = (float*)dsm;   // [4 mwarp][2 stat][128 col]
    if (l < 4) {
        const int mw = w >> 1;
        #pragma unroll
        for (int nf = 0; nf < 8; nf++) {
            const int colL = wn + nf*8 + l*2;
            red[(mw*2 + 0)*128 + colL]     = cs[2*nf];
            red[(mw*2 + 0)*128 + colL + 1] = cs[2*nf+1];
            red[(mw*2 + 1)*128 + colL]     = cq[2*nf];
            red[(mw*2 + 1)*128 + colL + 1] = cq[2*nf+1];
        }
    }
    __syncthreads();
    {
        const int colL = t & 127;
        const int stat = t >> 7;
        float v = red[(0*2 + stat)*128 + colL] + red[(1*2 + stat)*128 + colL]
                + red[(2*2 + stat)*128 + colL] + red[(3*2 + stat)*128 + colL];
        g_ps[stat][blockIdx.y][n0 + colL] = v;
    }
}

// ---------------- BN stats finalize ---------------------------------------
__global__ void stats2_kernel(const float* __restrict__ gamma,
                              const float* __restrict__ beta) {
    const int c = threadIdx.x;
    float s = 0.f, ss = 0.f;
    for (int k = 0; k < 128; k++) { s += g_ps[0][k][c]; ss += g_ps[1][k][c]; }
    const float inv_n = 1.0f / (float)MALL;
    float mean = s * inv_n;
    float var  = ss * inv_n - mean * mean;
    float sc = gamma[c] * rsqrtf(var + EPSbn);
    g_scale[c] = sc;
    g_shift[c] = beta[c] - mean * sc;
}

// ---------------- BN apply + ReLU + residual ------------------------------
__global__ void final_kernel(const float* __restrict__ x, float* __restrict__ out) {
    __shared__ float tile[64][65];
    const int s0 = blockIdx.x * 64;
    const int c0 = blockIdx.y * 64;
    const int b  = blockIdx.z;
    const int t  = threadIdx.x;

    const int lr = t >> 2, lc = (t & 3) * 16;
    #pragma unroll
    for (int q = 0; q < 4; q++) {
        float4 v = *(const float4*)&g_o[(size_t)(b*HW_ + s0 + lr) * C_ + c0 + lc + q*4];
        tile[lr][lc + q*4 + 0] = v.x; tile[lr][lc + q*4 + 1] = v.y;
        tile[lr][lc + q*4 + 2] = v.z; tile[lr][lc + q*4 + 3] = v.w;
    }
    __syncthreads();

    const int cl = t >> 2, sg = (t & 3) * 16;
    const int c = c0 + cl;
    const float sc = g_scale[c], sh = g_shift[c];
    const size_t base = ((size_t)b * C_ + c) * HW_ + s0 + sg;
    #pragma unroll
    for (int q = 0; q < 4; q++) {
        float4 xv = *(const float4*)&x[base + q*4];
        float4 w;
        w.x = fmaxf(tile[sg + q*4 + 0][cl] * sc + sh, 0.f) + xv.x;
        w.y = fmaxf(tile[sg + q*4 + 1][cl] * sc + sh, 0.f) + xv.y;
        w.z = fmaxf(tile[sg + q*4 + 2][cl] * sc + sh, 0.f) + xv.z;
        w.w = fmaxf(tile[sg + q*4 + 3][cl] * sc + sh, 0.f) + xv.w;
        *(float4*)&out[base + q*4] = w;
    }
}

// ---------------- launch: single stream, PDL overlap ----------------------
static void launch_proj_pdl(const float* x,
                            const float* gw, const float* gb,
                            const float* tw, const float* tb,
                            const float* pw, const float* pb, int b) {
    cudaLaunchConfig_t cfg = {};
    cfg.gridDim  = dim3(6, 64);
    cfg.blockDim = dim3(256);
    cfg.stream   = 0;
    cudaLaunchAttribute attr[1];
    attr[0].id = cudaLaunchAttributeProgrammaticStreamSerialization;
    attr[0].val.programmaticStreamSerializationAllowed = 1;
    cfg.attrs = attr;
    cfg.numAttrs = 1;
    if (cudaLaunchKernelEx(&cfg, proj_kernel, x, gw, gb, tw, tb, pw, pb, b)
        != cudaSuccess) {
        // fallback: plain launch (serial, still correct)
        proj_kernel<<<dim3(6, 64), 256>>>(x, gw, gb, tw, tb, pw, pb, b);
    }
}

extern "C" void kernel_launch(void* const* d_in, const int* in_sizes, int n_in,
                              void* d_out, int out_size) {
    const float* x     = (const float*)d_in[0];
    const float* gw    = (const float*)d_in[1];
    const float* gb    = (const float*)d_in[2];
    const float* tw    = (const float*)d_in[3];
    const float* tb    = (const float*)d_in[4];
    const float* pw    = (const float*)d_in[5];
    const float* pb    = (const float*)d_in[6];
    const float* ow    = (const float*)d_in[7];
    const float* ob    = (const float*)d_in[8];
    const float* gamma = (const float*)d_in[9];
    const float* beta  = (const float*)d_in[10];
    float* out = (float*)d_out;

    cudaFuncSetAttribute(attn_fused,  cudaFuncAttributeMaxDynamicSharedMemorySize, ATT_SMEM);
    cudaFuncSetAttribute(outconv_mma, cudaFuncAttributeMaxDynamicSharedMemorySize, 4 * OC_PLANE);

    wconv_kernel<<<dim3(128), 256>>>(ow);
    proj_kernel <<<dim3(6, 64), 256>>>(x, gw, gb, tw, tb, pw, pb, 0);
    for (int b = 0; b < 4; b++) {
        attn_fused<<<dim3(64), 128, ATT_SMEM>>>(b);
        if (b + 1 < 4)
            launch_proj_pdl(x, gw, gb, tw, tb, pw, pb, b + 1);  // overlaps attn(b)
    }
    outconv_mma  <<<dim3(2, 128),   256, 4 * OC_PLANE>>>(ob);
    stats2_kernel<<<dim3(1),        256>>>(gamma, beta);
    final_kernel <<<dim3(64, 4, 4), 256>>>(x, out);
}

// round 13
// speedup vs baseline: 1.7981x; 1.7981x over previous
#include <cuda_runtime.h>
#include <cuda_bf16.h>
#include <math.h>
#include <stdint.h>

#define B_   4
#define C_   256
#define CI_  128
#define HW_  4096
#define MALL (B_*HW_)          // 16384
#define EPSbn 1e-5f

// ---------------- static scratch (no allocations allowed) ----------------
__device__ __nv_bfloat16 g_th[(size_t)MALL * CI_];      // theta hi [m][ci]
__device__ __nv_bfloat16 g_tl[(size_t)MALL * CI_];      // theta lo
__device__ __nv_bfloat16 g_phh[(size_t)MALL * CI_];     // phi hi
__device__ __nv_bfloat16 g_phl[(size_t)MALL * CI_];     // phi lo
__device__ __nv_bfloat16 g_gh[(size_t)MALL * CI_];      // g hi [m][ci]
__device__ __nv_bfloat16 g_gl[(size_t)MALL * CI_];      // g lo
__device__ __nv_bfloat16 g_yh[(size_t)MALL * CI_];      // y hi
__device__ __nv_bfloat16 g_yl[(size_t)MALL * CI_];      // y lo
__device__ __nv_bfloat16 g_owh[(size_t)C_ * CI_];       // out_w hi
__device__ __nv_bfloat16 g_owl[(size_t)C_ * CI_];       // out_w lo
__device__ float g_o[(size_t)MALL * C_];
__device__ float g_ps[2][128][256];                     // per-128-row-chunk stats
__device__ float g_scale[C_];
__device__ float g_shift[C_];

// ---------------- portable tensor-core helpers (sm_80+ PTX) ---------------
__device__ __forceinline__ uint32_t smem_u32(const void* p) {
    uint32_t a;
    asm("{ .reg .u64 t; cvta.to.shared.u64 t, %1; cvt.u32.u64 %0, t; }" : "=r"(a) : "l"(p));
    return a;
}
__device__ __forceinline__ void ldsm4(uint32_t* r, uint32_t addr) {
    asm volatile("ldmatrix.sync.aligned.m8n8.x4.shared.b16 {%0,%1,%2,%3}, [%4];"
        : "=r"(r[0]), "=r"(r[1]), "=r"(r[2]), "=r"(r[3]) : "r"(addr));
}
__device__ __forceinline__ void ldsm4t(uint32_t* r, uint32_t addr) {
    asm volatile("ldmatrix.sync.aligned.m8n8.x4.trans.shared.b16 {%0,%1,%2,%3}, [%4];"
        : "=r"(r[0]), "=r"(r[1]), "=r"(r[2]), "=r"(r[3]) : "r"(addr));
}
__device__ __forceinline__ void mma_bf16(float* c, const uint32_t* a, const uint32_t* b) {
    asm volatile(
        "mma.sync.aligned.m16n8k16.row.col.f32.bf16.bf16.f32 "
        "{%0,%1,%2,%3}, {%4,%5,%6,%7}, {%8,%9}, {%0,%1,%2,%3};"
        : "+f"(c[0]), "+f"(c[1]), "+f"(c[2]), "+f"(c[3])
        : "r"(a[0]), "r"(a[1]), "r"(a[2]), "r"(a[3]), "r"(b[0]), "r"(b[1]));
}
__device__ __forceinline__ void split1(float v, __nv_bfloat16& h, __nv_bfloat16& l) {
    h = __float2bfloat16(v);
    l = __float2bfloat16(v - __bfloat162float(h));
}
__device__ __forceinline__ uint32_t pack2(__nv_bfloat16 a, __nv_bfloat16 b) {
    __nv_bfloat162 v; v.x = a; v.y = b;
    return *(uint32_t*)&v;
}
__device__ __forceinline__ void cpa16(uint32_t dst, const void* src) {
    asm volatile("cp.async.cg.shared.global [%0], [%1], 16;" :: "r"(dst), "l"(src));
}
#define CP_COMMIT() asm volatile("cp.async.commit_group;" ::: "memory")
#define CP_WAIT0()  asm volatile("cp.async.wait_group 0;" ::: "memory")

// ---------------- kernel 1: projections -> bf16 hi/lo planes [m][ci] ------
__global__ void proj_kernel(const float* __restrict__ x,
                            const float* __restrict__ gw,  const float* __restrict__ gb,
                            const float* __restrict__ tw,  const float* __restrict__ tb,
                            const float* __restrict__ pw,  const float* __restrict__ pb) {
    __shared__ float As[16][68];
    __shared__ float Bs[16][68];
    const int tid = threadIdx.x;
    const int n0 = blockIdx.x * 64;            // 0..383
    const int m0 = blockIdx.y * 64;
    const int b  = m0 / HW_;
    const int s0 = m0 % HW_;

    const float* wbase; const float* bbase; int j0;
    if      (n0 < 128) { wbase = gw; bbase = gb; j0 = n0;       }
    else if (n0 < 256) { wbase = tw; bbase = tb; j0 = n0 - 128; }
    else               { wbase = pw; bbase = pb; j0 = n0 - 256; }
    const int seg = n0 >> 7;

    const float* xb = x + (size_t)b * C_ * HW_;
    const int tx = tid & 15, ty = tid >> 4;
    float acc[4][4] = {};

    const int la_kk = tid >> 4, la_m4 = (tid & 15) * 4;
    const int lb_nn = tid >> 2, lb_k4 = (tid & 3) * 4;

    for (int k0 = 0; k0 < C_; k0 += 16) {
        float4 av = *(const float4*)&xb[(k0 + la_kk) * HW_ + s0 + la_m4];
        As[la_kk][la_m4+0] = av.x; As[la_kk][la_m4+1] = av.y;
        As[la_kk][la_m4+2] = av.z; As[la_kk][la_m4+3] = av.w;
        float4 bv = *(const float4*)&wbase[(j0 + lb_nn) * C_ + k0 + lb_k4];
        Bs[lb_k4+0][lb_nn] = bv.x; Bs[lb_k4+1][lb_nn] = bv.y;
        Bs[lb_k4+2][lb_nn] = bv.z; Bs[lb_k4+3][lb_nn] = bv.w;
        __syncthreads();
        #pragma unroll
        for (int kk = 0; kk < 16; kk++) {
            float a[4], bb[4];
            #pragma unroll
            for (int i = 0; i < 4; i++) a[i]  = As[kk][ty*4 + i];
            #pragma unroll
            for (int j = 0; j < 4; j++) bb[j] = Bs[kk][tx*4 + j];
            #pragma unroll
            for (int i = 0; i < 4; i++)
                #pragma unroll
                for (int j = 0; j < 4; j++) acc[i][j] += a[i] * bb[j];
        }
        __syncthreads();
    }

    __nv_bfloat16* ph = (seg == 0) ? g_gh : ((seg == 1) ? g_th : g_phh);
    __nv_bfloat16* pl = (seg == 0) ? g_gl : ((seg == 1) ? g_tl : g_phl);
    #pragma unroll
    for (int i = 0; i < 4; i++) {
        const int m = m0 + ty*4 + i;
        const int j = j0 + tx*4;
        union { __nv_bfloat16 h[4]; uint2 u; } H;
        union { __nv_bfloat16 l[4]; uint2 u; } L;
        #pragma unroll
        for (int jj = 0; jj < 4; jj++)
            split1(acc[i][jj] + bbase[j+jj], H.h[jj], L.l[jj]);
        *(uint2*)&ph[(size_t)m * CI_ + j] = H.u;
        *(uint2*)&pl[(size_t)m * CI_ + j] = L.u;
    }
}

// ---------------- kernel 1b: out_w -> bf16 hi/lo --------------------------
__global__ void wconv_kernel(const float* __restrict__ ow) {
    const int i = blockIdx.x * 256 + threadIdx.x;   // 0..32767
    split1(ow[i], g_owh[i], g_owl[i]);
}

// ---------------- kernel 2: fused flash attention, 4 warps, 2 CTA/SM ------
// grid (64 m-tiles, 4 b), block 128. MMA issue order pass-major so
// consecutive HMMA hit different accumulators (RAW distance 4).
#define ATT_SMEM 104448
__global__ __launch_bounds__(128, 2) void attn_fused() {
    extern __shared__ char sm[];
    const int t = threadIdx.x, w = t >> 5, l = t & 31;
    const int m0 = blockIdx.x * 64;
    const int b  = blockIdx.y;

    char* TH = sm;
    char* TL = sm + 17408;

    const size_t thbase = ((size_t)b * HW_ + m0) * CI_;
    const __nv_bfloat16* PhiH = g_phh + (size_t)b * HW_ * CI_;
    const __nv_bfloat16* PhiL = g_phl + (size_t)b * HW_ * CI_;
    const __nv_bfloat16* GHp  = g_gh  + (size_t)b * HW_ * CI_;
    const __nv_bfloat16* GLp  = g_gl  + (size_t)b * HW_ * CI_;

    for (int i = t; i < 1024; i += 128) {
        const int row = i >> 4, c16 = i & 15;
        cpa16(smem_u32(TH + row*272 + c16*16), g_th + thbase + (size_t)row*CI_ + c16*8);
        cpa16(smem_u32(TL + row*272 + c16*16), g_tl + thbase + (size_t)row*CI_ + c16*8);
    }

    auto load_chunk = [&](int buf, int n0) {
        char* base = sm + 34816 + buf * 34816;
        for (int i = t; i < 512; i += 128) {
            const int row = i >> 4, c16 = i & 15;
            const size_t so = (size_t)(n0 + row) * CI_ + c16 * 8;
            const int dof = row*272 + c16*16;
            cpa16(smem_u32(base +         dof), PhiH + so);
            cpa16(smem_u32(base +  8704 + dof), PhiL + so);
            cpa16(smem_u32(base + 17408 + dof), GHp + so);
            cpa16(smem_u32(base + 26112 + dof), GLp + so);
        }
    };

    load_chunk(0, 0);
    CP_COMMIT();

    const int wm = w * 16;

    const int a_row = (l & 7) + ((l >> 3) & 1) * 8;
    const int a_kb  = (l >> 4) * 8;
    const int b_row = (l & 7) + (l >> 4) * 8;
    const int b_kb  = ((l >> 3) & 1) * 8;
    const int y_row = (l & 7) + ((l >> 3) & 1) * 8;
    const int y_cb  = (l >> 4) * 8;
    const int qr = l >> 2, qc = (l & 3) * 2;

    float Y[16][4];
    #pragma unroll
    for (int i = 0; i < 16; i++)
        #pragma unroll
        for (int j = 0; j < 4; j++) Y[i][j] = 0.f;
    float rs0 = 0.f, rs1 = 0.f;

    for (int c = 0; c < 128; c++) {
        const int cur = c & 1;
        CP_WAIT0();
        __syncthreads();
        if (c + 1 < 128) { load_chunk(cur ^ 1, (c + 1) * 32); CP_COMMIT(); }

        char* FH = sm + 34816 + cur * 34816;
        char* FL = FH + 8704;
        char* GS = FH + 17408;
        char* GSL = FH + 26112;

        // ---- S = theta . phi^T (16 rows x 32 keys, K=128, bf16x3) ----
        float S[4][4];
        #pragma unroll
        for (int i = 0; i < 4; i++)
            #pragma unroll
            for (int j = 0; j < 4; j++) S[i][j] = 0.f;

        #pragma unroll
        for (int ks = 0; ks < 8; ks++) {
            uint32_t aH[4], aL[4];
            const int aoff = (wm + a_row) * 272 + (ks*16 + a_kb) * 2;
            ldsm4(aH, smem_u32(TH + aoff));
            ldsm4(aL, smem_u32(TL + aoff));
            uint32_t bH[4][2], bL[4][2];
            #pragma unroll
            for (int q = 0; q < 2; q++) {
                const int boff = (q*16 + b_row) * 272 + (ks*16 + b_kb) * 2;
                uint32_t r[4];
                ldsm4(r, smem_u32(FH + boff));
                bH[2*q][0] = r[0]; bH[2*q][1] = r[1];
                bH[2*q+1][0] = r[2]; bH[2*q+1][1] = r[3];
                ldsm4(r, smem_u32(FL + boff));
                bL[2*q][0] = r[0]; bL[2*q][1] = r[1];
                bL[2*q+1][0] = r[2]; bL[2*q+1][1] = r[3];
            }
            // pass-major issue: consecutive MMAs -> different accumulators
            #pragma unroll
            for (int nf = 0; nf < 4; nf++) mma_bf16(S[nf], aH, bH[nf]);
            #pragma unroll
            for (int nf = 0; nf < 4; nf++) mma_bf16(S[nf], aH, bL[nf]);
            #pragma unroll
            for (int nf = 0; nf < 4; nf++) mma_bf16(S[nf], aL, bH[nf]);
        }

        // ---- exp(s-20) in regs + rowsum ----
        #pragma unroll
        for (int nf = 0; nf < 4; nf++) {
            S[nf][0] = __expf(S[nf][0] - 20.0f);
            S[nf][1] = __expf(S[nf][1] - 20.0f);
            S[nf][2] = __expf(S[nf][2] - 20.0f);
            S[nf][3] = __expf(S[nf][3] - 20.0f);
            rs0 += S[nf][0] + S[nf][1];
            rs1 += S[nf][2] + S[nf][3];
        }

        // ---- Y += P . g  (A-frags from C-frags; trans B; pass-major) ----
        #pragma unroll
        for (int ks = 0; ks < 2; ks++) {
            uint32_t aH[4], aL[4];
            {
                __nv_bfloat16 h0,l0,h1,l1;
                const float* s0 = S[2*ks];
                const float* s1 = S[2*ks+1];
                split1(s0[0], h0, l0); split1(s0[1], h1, l1);
                aH[0] = pack2(h0, h1); aL[0] = pack2(l0, l1);
                split1(s0[2], h0, l0); split1(s0[3], h1, l1);
                aH[1] = pack2(h0, h1); aL[1] = pack2(l0, l1);
                split1(s1[0], h0, l0); split1(s1[1], h1, l1);
                aH[2] = pack2(h0, h1); aL[2] = pack2(l0, l1);
                split1(s1[2], h0, l0); split1(s1[3], h1, l1);
                aH[3] = pack2(h0, h1); aL[3] = pack2(l0, l1);
            }
            #pragma unroll
            for (int qp = 0; qp < 4; qp++) {    // column pairs: q = 2qp, 2qp+1
                uint32_t rh0[4], rl0[4], rh1[4], rl1[4];
                const int off0 = (ks*16 + y_row) * 272 + ((2*qp)*16 + y_cb) * 2;
                const int off1 = (ks*16 + y_row) * 272 + ((2*qp+1)*16 + y_cb) * 2;
                ldsm4t(rh0, smem_u32(GS  + off0));
                ldsm4t(rl0, smem_u32(GSL + off0));
                ldsm4t(rh1, smem_u32(GS  + off1));
                ldsm4t(rl1, smem_u32(GSL + off1));
                uint32_t bh[4][2] = {{rh0[0],rh0[1]},{rh0[2],rh0[3]},
                                     {rh1[0],rh1[1]},{rh1[2],rh1[3]}};
                uint32_t bl[4][2] = {{rl0[0],rl0[1]},{rl0[2],rl0[3]},
                                     {rl1[0],rl1[1]},{rl1[2],rl1[3]}};
                float* ya = Y[4*qp];
                // pass-major over 4 accumulators
                #pragma unroll
                for (int i = 0; i < 4; i++) mma_bf16(&ya[4*i], aH, bh[i]);
                #pragma unroll
                for (int i = 0; i < 4; i++) mma_bf16(&ya[4*i], aH, bl[i]);
                #pragma unroll
                for (int i = 0; i < 4; i++) mma_bf16(&ya[4*i], aL, bh[i]);
            }
        }
    }

    // ---- epilogue: quad rowsum reduce, normalize, bf16 hi/lo y ----
    rs0 += __shfl_xor_sync(0xffffffffu, rs0, 1);
    rs0 += __shfl_xor_sync(0xffffffffu, rs0, 2);
    rs1 += __shfl_xor_sync(0xffffffffu, rs1, 1);
    rs1 += __shfl_xor_sync(0xffffffffu, rs1, 2);
    const float ri0 = 1.0f / rs0;
    const float ri1 = 1.0f / rs1;

    const size_t yb = (size_t)b * HW_ + m0;
    const int r0 = wm + qr, r1 = r0 + 8;
    #pragma unroll
    for (int nf = 0; nf < 16; nf++) {
        const int col = nf*8 + qc;
        float v00 = Y[nf][0] * ri0, v01 = Y[nf][1] * ri0;
        float v10 = Y[nf][2] * ri1, v11 = Y[nf][3] * ri1;
        __nv_bfloat16 h0,l0,h1,l1;
        split1(v00, h0, l0); split1(v01, h1, l1);
        *(uint32_t*)&g_yh[(yb + r0) * CI_ + col] = pack2(h0, h1);
        *(uint32_t*)&g_yl[(yb + r0) * CI_ + col] = pack2(l0, l1);
        split1(v10, h0, l0); split1(v11, h1, l1);
        *(uint32_t*)&g_yh[(yb + r1) * CI_ + col] = pack2(h0, h1);
        *(uint32_t*)&g_yl[(yb + r1) * CI_ + col] = pack2(l0, l1);
    }
}

// ---------------- kernel 3: out conv via mma + fused BN partial stats -----
#define OC_PITCH 272
#define OC_PLANE (128 * OC_PITCH)   // 34816
__global__ __launch_bounds__(256, 1) void outconv_mma(const float* __restrict__ bias) {
    extern __shared__ char dsm[];
    const int t  = threadIdx.x;
    const int w  = t >> 5;
    const int l  = t & 31;
    const int m0 = blockIdx.y * 128;
    const int n0 = blockIdx.x * 128;

    char* Ah = dsm;
    char* Al = dsm + OC_PLANE;
    char* Bh = dsm + 2 * OC_PLANE;
    char* Bl = dsm + 3 * OC_PLANE;

    {
        const size_t ar = (size_t)m0 * CI_;
        const size_t br = (size_t)n0 * CI_;
        for (int i = t; i < 2048; i += 256) {
            const int row = i >> 4, c = i & 15;
            const size_t so = (size_t)row * CI_ + c * 8;
            const int dof = row * OC_PITCH + c * 16;
            cpa16(smem_u32(Ah + dof), g_yh  + ar + so);
            cpa16(smem_u32(Al + dof), g_yl  + ar + so);
            cpa16(smem_u32(Bh + dof), g_owh + br + so);
            cpa16(smem_u32(Bl + dof), g_owl + br + so);
        }
    }
    CP_COMMIT(); CP_WAIT0();
    __syncthreads();

    const int wm = (w >> 1) * 32;
    const int wn = (w & 1) * 64;

    float acc[2][8][4];
    #pragma unroll
    for (int i = 0; i < 2; i++)
        #pragma unroll
        for (int j = 0; j < 8; j++)
            #pragma unroll
            for (int k = 0; k < 4; k++) acc[i][j][k] = 0.f;

    const int a_row = (l & 7) + ((l >> 3) & 1) * 8;
    const int a_kb  = (l >> 4) * 8;
    const int b_row = (l & 7) + (l >> 4) * 8;
    const int b_kb  = ((l >> 3) & 1) * 8;

    #pragma unroll
    for (int ks = 0; ks < 8; ks++) {
        uint32_t aH[2][4], aL[2][4];
        #pragma unroll
        for (int mf = 0; mf < 2; mf++) {
            const int off = (wm + mf*16 + a_row) * OC_PITCH + (ks*16 + a_kb) * 2;
            ldsm4(aH[mf], smem_u32(Ah + off));
            ldsm4(aL[mf], smem_u32(Al + off));
        }
        uint32_t bH[8][2], bL[8][2];
        #pragma unroll
        for (int q = 0; q < 4; q++) {
            const int off = (wn + q*16 + b_row) * OC_PITCH + (ks*16 + b_kb) * 2;
            uint32_t r[4];
            ldsm4(r, smem_u32(Bh + off));
            bH[2*q][0] = r[0]; bH[2*q][1] = r[1]; bH[2*q+1][0] = r[2]; bH[2*q+1][1] = r[3];
            ldsm4(r, smem_u32(Bl + off));
            bL[2*q][0] = r[0]; bL[2*q][1] = r[1]; bL[2*q+1][0] = r[2]; bL[2*q+1][1] = r[3];
        }
        // pass-major issue order across all 16 accumulators
        #pragma unroll
        for (int mf = 0; mf < 2; mf++)
            #pragma unroll
            for (int nf = 0; nf < 8; nf++) mma_bf16(acc[mf][nf], aH[mf], bH[nf]);
        #pragma unroll
        for (int mf = 0; mf < 2; mf++)
            #pragma unroll
            for (int nf = 0; nf < 8; nf++) mma_bf16(acc[mf][nf], aH[mf], bL[nf]);
        #pragma unroll
        for (int mf = 0; mf < 2; mf++)
            #pragma unroll
            for (int nf = 0; nf < 8; nf++) mma_bf16(acc[mf][nf], aL[mf], bH[nf]);
    }

    // add bias, store o, accumulate per-col partial sums/sumsq
    const int qr = l >> 2, qc = (l & 3) * 2;
    float cs[16], cq[16];
    #pragma unroll
    for (int i = 0; i < 16; i++) { cs[i] = 0.f; cq[i] = 0.f; }

    #pragma unroll
    for (int mf = 0; mf < 2; mf++) {
        const int r0 = m0 + wm + mf*16 + qr;
        const int r1 = r0 + 8;
        #pragma unroll
        for (int nf = 0; nf < 8; nf++) {
            const int col = n0 + wn + nf*8 + qc;
            const float b0 = bias[col], b1 = bias[col+1];
            float v0 = acc[mf][nf][0] + b0, v1 = acc[mf][nf][1] + b1;
            float v2 = acc[mf][nf][2] + b0, v3 = acc[mf][nf][3] + b1;
            *(float2*)&g_o[(size_t)r0 * C_ + col] = make_float2(v0, v1);
            *(float2*)&g_o[(size_t)r1 * C_ + col] = make_float2(v2, v3);
            cs[2*nf]   += v0 + v2;  cq[2*nf]   += v0*v0 + v2*v2;
            cs[2*nf+1] += v1 + v3;  cq[2*nf+1] += v1*v1 + v3*v3;
        }
    }
    #pragma unroll
    for (int i = 0; i < 16; i++) {
        #pragma unroll
        for (int o = 4; o < 32; o <<= 1) {
            cs[i] += __shfl_xor_sync(0xffffffffu, cs[i], o);
            cq[i] += __shfl_xor_sync(0xffffffffu, cq[i], o);
        }
    }
    __syncthreads();
    float* red = (float*)dsm;   // [4 mwarp][2 stat][128 col]
    if (l < 4) {
        const int mw = w >> 1;
        #pragma unroll
        for (int nf = 0; nf < 8; nf++) {
            const int colL = wn + nf*8 + l*2;
            red[(mw*2 + 0)*128 + colL]     = cs[2*nf];
            red[(mw*2 + 0)*128 + colL + 1] = cs[2*nf+1];
            red[(mw*2 + 1)*128 + colL]     = cq[2*nf];
            red[(mw*2 + 1)*128 + colL + 1] = cq[2*nf+1];
        }
    }
    __syncthreads();
    {
        const int colL = t & 127;
        const int stat = t >> 7;
        float v = red[(0*2 + stat)*128 + colL] + red[(1*2 + stat)*128 + colL]
                + red[(2*2 + stat)*128 + colL] + red[(3*2 + stat)*128 + colL];
        g_ps[stat][blockIdx.y][n0 + colL] = v;
    }
}

// ---------------- BN stats finalize ---------------------------------------
__global__ void stats2_kernel(const float* __restrict__ gamma,
                              const float* __restrict__ beta) {
    const int c = threadIdx.x;
    float s = 0.f, ss = 0.f;
    for (int k = 0; k < 128; k++) { s += g_ps[0][k][c]; ss += g_ps[1][k][c]; }
    const float inv_n = 1.0f / (float)MALL;
    float mean = s * inv_n;
    float var  = ss * inv_n - mean * mean;
    float sc = gamma[c] * rsqrtf(var + EPSbn);
    g_scale[c] = sc;
    g_shift[c] = beta[c] - mean * sc;
}

// ---------------- BN apply + ReLU + residual ------------------------------
__global__ void final_kernel(const float* __restrict__ x, float* __restrict__ out) {
    __shared__ float tile[64][65];
    const int s0 = blockIdx.x * 64;
    const int c0 = blockIdx.y * 64;
    const int b  = blockIdx.z;
    const int t  = threadIdx.x;

    const int lr = t >> 2, lc = (t & 3) * 16;
    #pragma unroll
    for (int q = 0; q < 4; q++) {
        float4 v = *(const float4*)&g_o[(size_t)(b*HW_ + s0 + lr) * C_ + c0 + lc + q*4];
        tile[lr][lc + q*4 + 0] = v.x; tile[lr][lc + q*4 + 1] = v.y;
        tile[lr][lc + q*4 + 2] = v.z; tile[lr][lc + q*4 + 3] = v.w;
    }
    __syncthreads();

    const int cl = t >> 2, sg = (t & 3) * 16;
    const int c = c0 + cl;
    const float sc = g_scale[c], sh = g_shift[c];
    const size_t base = ((size_t)b * C_ + c) * HW_ + s0 + sg;
    #pragma unroll
    for (int q = 0; q < 4; q++) {
        float4 xv = *(const float4*)&x[base + q*4];
        float4 w;
        w.x = fmaxf(tile[sg + q*4 + 0][cl] * sc + sh, 0.f) + xv.x;
        w.y = fmaxf(tile[sg + q*4 + 1][cl] * sc + sh, 0.f) + xv.y;
        w.z = fmaxf(tile[sg + q*4 + 2][cl] * sc + sh, 0.f) + xv.z;
        w.w = fmaxf(tile[sg + q*4 + 3][cl] * sc + sh, 0.f) + xv.w;
        *(float4*)&out[base + q*4] = w;
    }
}

// ---------------- launch: serial single stream ----------------------------
extern "C" void kernel_launch(void* const* d_in, const int* in_sizes, int n_in,
                              void* d_out, int out_size) {
    const float* x     = (const float*)d_in[0];
    const float* gw    = (const float*)d_in[1];
    const float* gb    = (const float*)d_in[2];
    const float* tw    = (const float*)d_in[3];
    const float* tb    = (const float*)d_in[4];
    const float* pw    = (const float*)d_in[5];
    const float* pb    = (const float*)d_in[6];
    const float* ow    = (const float*)d_in[7];
    const float* ob    = (const float*)d_in[8];
    const float* gamma = (const float*)d_in[9];
    const float* beta  = (const float*)d_in[10];
    float* out = (float*)d_out;

    cudaFuncSetAttribute(attn_fused,  cudaFuncAttributeMaxDynamicSharedMemorySize, ATT_SMEM);
    cudaFuncSetAttribute(outconv_mma, cudaFuncAttributeMaxDynamicSharedMemorySize, 4 * OC_PLANE);

    wconv_kernel <<<dim3(128),      256>>>(ow);
    proj_kernel  <<<dim3(6, 256),   256>>>(x, gw, gb, tw, tb, pw, pb);
    attn_fused   <<<dim3(64, 4),    128, ATT_SMEM>>>();
    outconv_mma  <<<dim3(2, 128),   256, 4 * OC_PLANE>>>(ob);
    stats2_kernel<<<dim3(1),        256>>>(gamma, beta);
    final_kernel <<<dim3(64, 4, 4), 256>>>(x, out);
}

// round 14
// speedup vs baseline: 1.8061x; 1.0044x over previous
#include <cuda_runtime.h>
#include <cuda_bf16.h>
#include <math.h>
#include <stdint.h>

#define B_   4
#define C_   256
#define CI_  128
#define HW_  4096
#define MALL (B_*HW_)          // 16384
#define EPSbn 1e-5f

// ---------------- static scratch (no allocations allowed) ----------------
__device__ __nv_bfloat16 g_th[(size_t)MALL * CI_];      // theta hi [m][ci]
__device__ __nv_bfloat16 g_tl[(size_t)MALL * CI_];      // theta lo
__device__ __nv_bfloat16 g_phh[(size_t)MALL * CI_];     // phi hi
__device__ __nv_bfloat16 g_phl[(size_t)MALL * CI_];     // phi lo
__device__ __nv_bfloat16 g_gh[(size_t)MALL * CI_];      // g hi [m][ci]
__device__ __nv_bfloat16 g_gl[(size_t)MALL * CI_];      // g lo
__device__ __nv_bfloat16 g_yh[(size_t)MALL * CI_];      // y hi
__device__ __nv_bfloat16 g_yl[(size_t)MALL * CI_];      // y lo
__device__ __nv_bfloat16 g_owh[(size_t)C_ * CI_];       // out_w hi
__device__ __nv_bfloat16 g_owl[(size_t)C_ * CI_];       // out_w lo
__device__ float g_o[(size_t)MALL * C_];
__device__ float g_ps[2][128][256];                     // per-128-row-chunk stats
__device__ float g_scale[C_];
__device__ float g_shift[C_];

// ---------------- portable tensor-core helpers (sm_80+ PTX) ---------------
__device__ __forceinline__ uint32_t smem_u32(const void* p) {
    uint32_t a;
    asm("{ .reg .u64 t; cvta.to.shared.u64 t, %1; cvt.u32.u64 %0, t; }" : "=r"(a) : "l"(p));
    return a;
}
__device__ __forceinline__ void ldsm4(uint32_t* r, uint32_t addr) {
    asm volatile("ldmatrix.sync.aligned.m8n8.x4.shared.b16 {%0,%1,%2,%3}, [%4];"
        : "=r"(r[0]), "=r"(r[1]), "=r"(r[2]), "=r"(r[3]) : "r"(addr));
}
__device__ __forceinline__ void ldsm4t(uint32_t* r, uint32_t addr) {
    asm volatile("ldmatrix.sync.aligned.m8n8.x4.trans.shared.b16 {%0,%1,%2,%3}, [%4];"
        : "=r"(r[0]), "=r"(r[1]), "=r"(r[2]), "=r"(r[3]) : "r"(addr));
}
__device__ __forceinline__ void mma_bf16(float* c, const uint32_t* a, const uint32_t* b) {
    asm volatile(
        "mma.sync.aligned.m16n8k16.row.col.f32.bf16.bf16.f32 "
        "{%0,%1,%2,%3}, {%4,%5,%6,%7}, {%8,%9}, {%0,%1,%2,%3};"
        : "+f"(c[0]), "+f"(c[1]), "+f"(c[2]), "+f"(c[3])
        : "r"(a[0]), "r"(a[1]), "r"(a[2]), "r"(a[3]), "r"(b[0]), "r"(b[1]));
}
__device__ __forceinline__ void split1(float v, __nv_bfloat16& h, __nv_bfloat16& l) {
    h = __float2bfloat16(v);
    l = __float2bfloat16(v - __bfloat162float(h));
}
__device__ __forceinline__ uint32_t pack2(__nv_bfloat16 a, __nv_bfloat16 b) {
    __nv_bfloat162 v; v.x = a; v.y = b;
    return *(uint32_t*)&v;
}
__device__ __forceinline__ void cpa16(uint32_t dst, const void* src) {
    asm volatile("cp.async.cg.shared.global [%0], [%1], 16;" :: "r"(dst), "l"(src));
}
#define CP_COMMIT() asm volatile("cp.async.commit_group;" ::: "memory")
#define CP_WAIT0()  asm volatile("cp.async.wait_group 0;" ::: "memory")

// ---------------- kernel 1: projections -> bf16 hi/lo planes [m][ci] ------
__global__ void proj_kernel(const float* __restrict__ x,
                            const float* __restrict__ gw,  const float* __restrict__ gb,
                            const float* __restrict__ tw,  const float* __restrict__ tb,
                            const float* __restrict__ pw,  const float* __restrict__ pb) {
    __shared__ float As[16][68];
    __shared__ float Bs[16][68];
    const int tid = threadIdx.x;
    const int n0 = blockIdx.x * 64;            // 0..383
    const int m0 = blockIdx.y * 64;
    const int b  = m0 / HW_;
    const int s0 = m0 % HW_;

    const float* wbase; const float* bbase; int j0;
    if      (n0 < 128) { wbase = gw; bbase = gb; j0 = n0;       }
    else if (n0 < 256) { wbase = tw; bbase = tb; j0 = n0 - 128; }
    else               { wbase = pw; bbase = pb; j0 = n0 - 256; }
    const int seg = n0 >> 7;

    const float* xb = x + (size_t)b * C_ * HW_;
    const int tx = tid & 15, ty = tid >> 4;
    float acc[4][4] = {};

    const int la_kk = tid >> 4, la_m4 = (tid & 15) * 4;
    const int lb_nn = tid >> 2, lb_k4 = (tid & 3) * 4;

    for (int k0 = 0; k0 < C_; k0 += 16) {
        float4 av = *(const float4*)&xb[(k0 + la_kk) * HW_ + s0 + la_m4];
        As[la_kk][la_m4+0] = av.x; As[la_kk][la_m4+1] = av.y;
        As[la_kk][la_m4+2] = av.z; As[la_kk][la_m4+3] = av.w;
        float4 bv = *(const float4*)&wbase[(j0 + lb_nn) * C_ + k0 + lb_k4];
        Bs[lb_k4+0][lb_nn] = bv.x; Bs[lb_k4+1][lb_nn] = bv.y;
        Bs[lb_k4+2][lb_nn] = bv.z; Bs[lb_k4+3][lb_nn] = bv.w;
        __syncthreads();
        #pragma unroll
        for (int kk = 0; kk < 16; kk++) {
            float a[4], bb[4];
            #pragma unroll
            for (int i = 0; i < 4; i++) a[i]  = As[kk][ty*4 + i];
            #pragma unroll
            for (int j = 0; j < 4; j++) bb[j] = Bs[kk][tx*4 + j];
            #pragma unroll
            for (int i = 0; i < 4; i++)
                #pragma unroll
                for (int j = 0; j < 4; j++) acc[i][j] += a[i] * bb[j];
        }
        __syncthreads();
    }

    __nv_bfloat16* ph = (seg == 0) ? g_gh : ((seg == 1) ? g_th : g_phh);
    __nv_bfloat16* pl = (seg == 0) ? g_gl : ((seg == 1) ? g_tl : g_phl);
    #pragma unroll
    for (int i = 0; i < 4; i++) {
        const int m = m0 + ty*4 + i;
        const int j = j0 + tx*4;
        union { __nv_bfloat16 h[4]; uint2 u; } H;
        union { __nv_bfloat16 l[4]; uint2 u; } L;
        #pragma unroll
        for (int jj = 0; jj < 4; jj++)
            split1(acc[i][jj] + bbase[j+jj], H.h[jj], L.l[jj]);
        *(uint2*)&ph[(size_t)m * CI_ + j] = H.u;
        *(uint2*)&pl[(size_t)m * CI_ + j] = L.u;
    }
}

// ---------------- kernel 1b: out_w -> bf16 hi/lo --------------------------
__global__ void wconv_kernel(const float* __restrict__ ow) {
    const int i = blockIdx.x * 256 + threadIdx.x;   // 0..32767
    split1(ow[i], g_owh[i], g_owl[i]);
}

// ---------------- kernel 2: fused flash attention, pipelined frags --------
#define ATT_SMEM 104448
__global__ __launch_bounds__(128, 2) void attn_fused() {
    extern __shared__ char sm[];
    const int t = threadIdx.x, w = t >> 5, l = t & 31;
    const int m0 = blockIdx.x * 64;
    const int b  = blockIdx.y;

    char* TH = sm;
    char* TL = sm + 17408;

    const size_t thbase = ((size_t)b * HW_ + m0) * CI_;
    const __nv_bfloat16* PhiH = g_phh + (size_t)b * HW_ * CI_;
    const __nv_bfloat16* PhiL = g_phl + (size_t)b * HW_ * CI_;
    const __nv_bfloat16* GHp  = g_gh  + (size_t)b * HW_ * CI_;
    const __nv_bfloat16* GLp  = g_gl  + (size_t)b * HW_ * CI_;

    for (int i = t; i < 1024; i += 128) {
        const int row = i >> 4, c16 = i & 15;
        cpa16(smem_u32(TH + row*272 + c16*16), g_th + thbase + (size_t)row*CI_ + c16*8);
        cpa16(smem_u32(TL + row*272 + c16*16), g_tl + thbase + (size_t)row*CI_ + c16*8);
    }

    auto load_chunk = [&](int buf, int n0) {
        char* base = sm + 34816 + buf * 34816;
        for (int i = t; i < 512; i += 128) {
            const int row = i >> 4, c16 = i & 15;
            const size_t so = (size_t)(n0 + row) * CI_ + c16 * 8;
            const int dof = row*272 + c16*16;
            cpa16(smem_u32(base +         dof), PhiH + so);
            cpa16(smem_u32(base +  8704 + dof), PhiL + so);
            cpa16(smem_u32(base + 17408 + dof), GHp + so);
            cpa16(smem_u32(base + 26112 + dof), GLp + so);
        }
    };

    load_chunk(0, 0);
    CP_COMMIT();

    const int wm = w * 16;

    const int a_row = (l & 7) + ((l >> 3) & 1) * 8;
    const int a_kb  = (l >> 4) * 8;
    const int b_row = (l & 7) + (l >> 4) * 8;
    const int b_kb  = ((l >> 3) & 1) * 8;
    const int y_row = (l & 7) + ((l >> 3) & 1) * 8;
    const int y_cb  = (l >> 4) * 8;
    const int qr = l >> 2, qc = (l & 3) * 2;

    float Y[16][4];
    #pragma unroll
    for (int i = 0; i < 16; i++)
        #pragma unroll
        for (int j = 0; j < 4; j++) Y[i][j] = 0.f;
    float rs0 = 0.f, rs1 = 0.f;

    for (int c = 0; c < 128; c++) {
        const int cur = c & 1;
        CP_WAIT0();
        __syncthreads();
        if (c + 1 < 128) { load_chunk(cur ^ 1, (c + 1) * 32); CP_COMMIT(); }

        char* FH = sm + 34816 + cur * 34816;
        char* FL = FH + 8704;
        char* GS = FH + 17408;
        char* GSL = FH + 26112;

        // ---- S = theta . phi^T (pipelined fragment double-buffer) ----
        float S[4][4];
        #pragma unroll
        for (int i = 0; i < 4; i++)
            #pragma unroll
            for (int j = 0; j < 4; j++) S[i][j] = 0.f;

        uint32_t aHp[2][4], aLp[2][4], bHp[2][4][2], bLp[2][4][2];
        auto loadSfrag = [&](int ks, int pb) {
            const int aoff = (wm + a_row) * 272 + (ks*16 + a_kb) * 2;
            ldsm4(aHp[pb], smem_u32(TH + aoff));
            ldsm4(aLp[pb], smem_u32(TL + aoff));
            #pragma unroll
            for (int q = 0; q < 2; q++) {
                const int boff = (q*16 + b_row) * 272 + (ks*16 + b_kb) * 2;
                uint32_t r[4];
                ldsm4(r, smem_u32(FH + boff));
                bHp[pb][2*q][0] = r[0]; bHp[pb][2*q][1] = r[1];
                bHp[pb][2*q+1][0] = r[2]; bHp[pb][2*q+1][1] = r[3];
                ldsm4(r, smem_u32(FL + boff));
                bLp[pb][2*q][0] = r[0]; bLp[pb][2*q][1] = r[1];
                bLp[pb][2*q+1][0] = r[2]; bLp[pb][2*q+1][1] = r[3];
            }
        };

        loadSfrag(0, 0);
        #pragma unroll
        for (int ks = 0; ks < 8; ks++) {
            const int pb = ks & 1;
            if (ks + 1 < 8) loadSfrag(ks + 1, pb ^ 1);
            #pragma unroll
            for (int nf = 0; nf < 4; nf++) mma_bf16(S[nf], aHp[pb], bHp[pb][nf]);
            #pragma unroll
            for (int nf = 0; nf < 4; nf++) mma_bf16(S[nf], aHp[pb], bLp[pb][nf]);
            #pragma unroll
            for (int nf = 0; nf < 4; nf++) mma_bf16(S[nf], aLp[pb], bHp[pb][nf]);
        }

        // ---- exp(s-20) in regs + rowsum ----
        #pragma unroll
        for (int nf = 0; nf < 4; nf++) {
            S[nf][0] = __expf(S[nf][0] - 20.0f);
            S[nf][1] = __expf(S[nf][1] - 20.0f);
            S[nf][2] = __expf(S[nf][2] - 20.0f);
            S[nf][3] = __expf(S[nf][3] - 20.0f);
            rs0 += S[nf][0] + S[nf][1];
            rs1 += S[nf][2] + S[nf][3];
        }

        // ---- build both ks A-frags up front ----
        uint32_t aHY[2][4], aLY[2][4];
        #pragma unroll
        for (int ks = 0; ks < 2; ks++) {
            __nv_bfloat16 h0,l0,h1,l1;
            const float* s0 = S[2*ks];
            const float* s1 = S[2*ks+1];
            split1(s0[0], h0, l0); split1(s0[1], h1, l1);
            aHY[ks][0] = pack2(h0, h1); aLY[ks][0] = pack2(l0, l1);
            split1(s0[2], h0, l0); split1(s0[3], h1, l1);
            aHY[ks][1] = pack2(h0, h1); aLY[ks][1] = pack2(l0, l1);
            split1(s1[0], h0, l0); split1(s1[1], h1, l1);
            aHY[ks][2] = pack2(h0, h1); aLY[ks][2] = pack2(l0, l1);
            split1(s1[2], h0, l0); split1(s1[3], h1, l1);
            aHY[ks][3] = pack2(h0, h1); aLY[ks][3] = pack2(l0, l1);
        }

        // ---- Y += P . g  (pipelined B-fragment double-buffer) ----
        uint32_t bhY[2][4][2], blY[2][4][2];
        auto loadYfrag = [&](int it, int pb) {
            const int ks = it >> 2, qp = it & 3;
            const int off0 = (ks*16 + y_row) * 272 + ((2*qp)*16 + y_cb) * 2;
            uint32_t rh0[4], rl0[4], rh1[4], rl1[4];
            ldsm4t(rh0, smem_u32(GS  + off0));
            ldsm4t(rl0, smem_u32(GSL + off0));
            ldsm4t(rh1, smem_u32(GS  + off0 + 32));
            ldsm4t(rl1, smem_u32(GSL + off0 + 32));
            bhY[pb][0][0] = rh0[0]; bhY[pb][0][1] = rh0[1];
            bhY[pb][1][0] = rh0[2]; bhY[pb][1][1] = rh0[3];
            bhY[pb][2][0] = rh1[0]; bhY[pb][2][1] = rh1[1];
            bhY[pb][3][0] = rh1[2]; bhY[pb][3][1] = rh1[3];
            blY[pb][0][0] = rl0[0]; blY[pb][0][1] = rl0[1];
            blY[pb][1][0] = rl0[2]; blY[pb][1][1] = rl0[3];
            blY[pb][2][0] = rl1[0]; blY[pb][2][1] = rl1[1];
            blY[pb][3][0] = rl1[2]; blY[pb][3][1] = rl1[3];
        };

        loadYfrag(0, 0);
        #pragma unroll
        for (int it = 0; it < 8; it++) {
            const int pb = it & 1;
            if (it + 1 < 8) loadYfrag(it + 1, pb ^ 1);
            const int ks = it >> 2, qp = it & 3;
            float* ya = Y[4*qp];
            #pragma unroll
            for (int i = 0; i < 4; i++) mma_bf16(&ya[4*i], aHY[ks], bhY[pb][i]);
            #pragma unroll
            for (int i = 0; i < 4; i++) mma_bf16(&ya[4*i], aHY[ks], blY[pb][i]);
            #pragma unroll
            for (int i = 0; i < 4; i++) mma_bf16(&ya[4*i], aLY[ks], bhY[pb][i]);
        }
    }

    // ---- epilogue: quad rowsum reduce, normalize, bf16 hi/lo y ----
    rs0 += __shfl_xor_sync(0xffffffffu, rs0, 1);
    rs0 += __shfl_xor_sync(0xffffffffu, rs0, 2);
    rs1 += __shfl_xor_sync(0xffffffffu, rs1, 1);
    rs1 += __shfl_xor_sync(0xffffffffu, rs1, 2);
    const float ri0 = 1.0f / rs0;
    const float ri1 = 1.0f / rs1;

    const size_t yb = (size_t)b * HW_ + m0;
    const int r0 = wm + qr, r1 = r0 + 8;
    #pragma unroll
    for (int nf = 0; nf < 16; nf++) {
        const int col = nf*8 + qc;
        float v00 = Y[nf][0] * ri0, v01 = Y[nf][1] * ri0;
        float v10 = Y[nf][2] * ri1, v11 = Y[nf][3] * ri1;
        __nv_bfloat16 h0,l0,h1,l1;
        split1(v00, h0, l0); split1(v01, h1, l1);
        *(uint32_t*)&g_yh[(yb + r0) * CI_ + col] = pack2(h0, h1);
        *(uint32_t*)&g_yl[(yb + r0) * CI_ + col] = pack2(l0, l1);
        split1(v10, h0, l0); split1(v11, h1, l1);
        *(uint32_t*)&g_yh[(yb + r1) * CI_ + col] = pack2(h0, h1);
        *(uint32_t*)&g_yl[(yb + r1) * CI_ + col] = pack2(l0, l1);
    }
}

// ---------------- kernel 3: out conv via mma + fused BN partial stats -----
#define OC_PITCH 272
#define OC_PLANE (128 * OC_PITCH)   // 34816
__global__ __launch_bounds__(256, 1) void outconv_mma(const float* __restrict__ bias) {
    extern __shared__ char dsm[];
    const int t  = threadIdx.x;
    const int w  = t >> 5;
    const int l  = t & 31;
    const int m0 = blockIdx.y * 128;
    const int n0 = blockIdx.x * 128;

    char* Ah = dsm;
    char* Al = dsm + OC_PLANE;
    char* Bh = dsm + 2 * OC_PLANE;
    char* Bl = dsm + 3 * OC_PLANE;

    {
        const size_t ar = (size_t)m0 * CI_;
        const size_t br = (size_t)n0 * CI_;
        for (int i = t; i < 2048; i += 256) {
            const int row = i >> 4, c = i & 15;
            const size_t so = (size_t)row * CI_ + c * 8;
            const int dof = row * OC_PITCH + c * 16;
            cpa16(smem_u32(Ah + dof), g_yh  + ar + so);
            cpa16(smem_u32(Al + dof), g_yl  + ar + so);
            cpa16(smem_u32(Bh + dof), g_owh + br + so);
            cpa16(smem_u32(Bl + dof), g_owl + br + so);
        }
    }
    CP_COMMIT(); CP_WAIT0();
    __syncthreads();

    const int wm = (w >> 1) * 32;
    const int wn = (w & 1) * 64;

    float acc[2][8][4];
    #pragma unroll
    for (int i = 0; i < 2; i++)
        #pragma unroll
        for (int j = 0; j < 8; j++)
            #pragma unroll
            for (int k = 0; k < 4; k++) acc[i][j][k] = 0.f;

    const int a_row = (l & 7) + ((l >> 3) & 1) * 8;
    const int a_kb  = (l >> 4) * 8;
    const int b_row = (l & 7) + (l >> 4) * 8;
    const int b_kb  = ((l >> 3) & 1) * 8;

    #pragma unroll
    for (int ks = 0; ks < 8; ks++) {
        uint32_t aH[2][4], aL[2][4];
        #pragma unroll
        for (int mf = 0; mf < 2; mf++) {
            const int off = (wm + mf*16 + a_row) * OC_PITCH + (ks*16 + a_kb) * 2;
            ldsm4(aH[mf], smem_u32(Ah + off));
            ldsm4(aL[mf], smem_u32(Al + off));
        }
        uint32_t bH[8][2], bL[8][2];
        #pragma unroll
        for (int q = 0; q < 4; q++) {
            const int off = (wn + q*16 + b_row) * OC_PITCH + (ks*16 + b_kb) * 2;
            uint32_t r[4];
            ldsm4(r, smem_u32(Bh + off));
            bH[2*q][0] = r[0]; bH[2*q][1] = r[1]; bH[2*q+1][0] = r[2]; bH[2*q+1][1] = r[3];
            ldsm4(r, smem_u32(Bl + off));
            bL[2*q][0] = r[0]; bL[2*q][1] = r[1]; bL[2*q+1][0] = r[2]; bL[2*q+1][1] = r[3];
        }
        #pragma unroll
        for (int mf = 0; mf < 2; mf++)
            #pragma unroll
            for (int nf = 0; nf < 8; nf++) mma_bf16(acc[mf][nf], aH[mf], bH[nf]);
        #pragma unroll
        for (int mf = 0; mf < 2; mf++)
            #pragma unroll
            for (int nf = 0; nf < 8; nf++) mma_bf16(acc[mf][nf], aH[mf], bL[nf]);
        #pragma unroll
        for (int mf = 0; mf < 2; mf++)
            #pragma unroll
            for (int nf = 0; nf < 8; nf++) mma_bf16(acc[mf][nf], aL[mf], bH[nf]);
    }

    // add bias, store o, accumulate per-col partial sums/sumsq
    const int qr = l >> 2, qc = (l & 3) * 2;
    float cs[16], cq[16];
    #pragma unroll
    for (int i = 0; i < 16; i++) { cs[i] = 0.f; cq[i] = 0.f; }

    #pragma unroll
    for (int mf = 0; mf < 2; mf++) {
        const int r0 = m0 + wm + mf*16 + qr;
        const int r1 = r0 + 8;
        #pragma unroll
        for (int nf = 0; nf < 8; nf++) {
            const int col = n0 + wn + nf*8 + qc;
            const float b0 = bias[col], b1 = bias[col+1];
            float v0 = acc[mf][nf][0] + b0, v1 = acc[mf][nf][1] + b1;
            float v2 = acc[mf][nf][2] + b0, v3 = acc[mf][nf][3] + b1;
            *(float2*)&g_o[(size_t)r0 * C_ + col] = make_float2(v0, v1);
            *(float2*)&g_o[(size_t)r1 * C_ + col] = make_float2(v2, v3);
            cs[2*nf]   += v0 + v2;  cq[2*nf]   += v0*v0 + v2*v2;
            cs[2*nf+1] += v1 + v3;  cq[2*nf+1] += v1*v1 + v3*v3;
        }
    }
    #pragma unroll
    for (int i = 0; i < 16; i++) {
        #pragma unroll
        for (int o = 4; o < 32; o <<= 1) {
            cs[i] += __shfl_xor_sync(0xffffffffu, cs[i], o);
            cq[i] += __shfl_xor_sync(0xffffffffu, cq[i], o);
        }
    }
    __syncthreads();
    float* red = (float*)dsm;   // [4 mwarp][2 stat][128 col]
    if (l < 4) {
        const int mw = w >> 1;
        #pragma unroll
        for (int nf = 0; nf < 8; nf++) {
            const int colL = wn + nf*8 + l*2;
            red[(mw*2 + 0)*128 + colL]     = cs[2*nf];
            red[(mw*2 + 0)*128 + colL + 1] = cs[2*nf+1];
            red[(mw*2 + 1)*128 + colL]     = cq[2*nf];
            red[(mw*2 + 1)*128 + colL + 1] = cq[2*nf+1];
        }
    }
    __syncthreads();
    {
        const int colL = t & 127;
        const int stat = t >> 7;
        float v = red[(0*2 + stat)*128 + colL] + red[(1*2 + stat)*128 + colL]
                + red[(2*2 + stat)*128 + colL] + red[(3*2 + stat)*128 + colL];
        g_ps[stat][blockIdx.y][n0 + colL] = v;
    }
}

// ---------------- BN stats finalize ---------------------------------------
__global__ void stats2_kernel(const float* __restrict__ gamma,
                              const float* __restrict__ beta) {
    const int c = threadIdx.x;
    float s = 0.f, ss = 0.f;
    for (int k = 0; k < 128; k++) { s += g_ps[0][k][c]; ss += g_ps[1][k][c]; }
    const float inv_n = 1.0f / (float)MALL;
    float mean = s * inv_n;
    float var  = ss * inv_n - mean * mean;
    float sc = gamma[c] * rsqrtf(var + EPSbn);
    g_scale[c] = sc;
    g_shift[c] = beta[c] - mean * sc;
}

// ---------------- BN apply + ReLU + residual (x prefetched) ---------------
__global__ void final_kernel(const float* __restrict__ x, float* __restrict__ out) {
    __shared__ float tile[64][65];
    const int s0 = blockIdx.x * 64;
    const int c0 = blockIdx.y * 64;
    const int b  = blockIdx.z;
    const int t  = threadIdx.x;

    // prefetch residual x early (independent of smem phase)
    const int cl = t >> 2, sg = (t & 3) * 16;
    const int c = c0 + cl;
    const size_t base = ((size_t)b * C_ + c) * HW_ + s0 + sg;
    float4 xv[4];
    #pragma unroll
    for (int q = 0; q < 4; q++) xv[q] = *(const float4*)&x[base + q*4];

    const int lr = t >> 2, lc = (t & 3) * 16;
    #pragma unroll
    for (int q = 0; q < 4; q++) {
        float4 v = *(const float4*)&g_o[(size_t)(b*HW_ + s0 + lr) * C_ + c0 + lc + q*4];
        tile[lr][lc + q*4 + 0] = v.x; tile[lr][lc + q*4 + 1] = v.y;
        tile[lr][lc + q*4 + 2] = v.z; tile[lr][lc + q*4 + 3] = v.w;
    }
    __syncthreads();

    const float sc = g_scale[c], sh = g_shift[c];
    #pragma unroll
    for (int q = 0; q < 4; q++) {
        float4 w;
        w.x = fmaxf(tile[sg + q*4 + 0][cl] * sc + sh, 0.f) + xv[q].x;
        w.y = fmaxf(tile[sg + q*4 + 1][cl] * sc + sh, 0.f) + xv[q].y;
        w.z = fmaxf(tile[sg + q*4 + 2][cl] * sc + sh, 0.f) + xv[q].z;
        w.w = fmaxf(tile[sg + q*4 + 3][cl] * sc + sh, 0.f) + xv[q].w;
        *(float4*)&out[base + q*4] = w;
    }
}

// ---------------- launch: serial single stream ----------------------------
extern "C" void kernel_launch(void* const* d_in, const int* in_sizes, int n_in,
                              void* d_out, int out_size) {
    const float* x     = (const float*)d_in[0];
    const float* gw    = (const float*)d_in[1];
    const float* gb    = (const float*)d_in[2];
    const float* tw    = (const float*)d_in[3];
    const float* tb    = (const float*)d_in[4];
    const float* pw    = (const float*)d_in[5];
    const float* pb    = (const float*)d_in[6];
    const float* ow    = (const float*)d_in[7];
    const float* ob    = (const float*)d_in[8];
    const float* gamma = (const float*)d_in[9];
    const float* beta  = (const float*)d_in[10];
    float* out = (float*)d_out;

    cudaFuncSetAttribute(attn_fused,  cudaFuncAttributeMaxDynamicSharedMemorySize, ATT_SMEM);
    cudaFuncSetAttribute(outconv_mma, cudaFuncAttributeMaxDynamicSharedMemorySize, 4 * OC_PLANE);

    wconv_kernel <<<dim3(128),      256>>>(ow);
    proj_kernel  <<<dim3(6, 256),   256>>>(x, gw, gb, tw, tb, pw, pb);
    attn_fused   <<<dim3(64, 4),    128, ATT_SMEM>>>();
    outconv_mma  <<<dim3(2, 128),   256, 4 * OC_PLANE>>>(ob);
    stats2_kernel<<<dim3(1),        256>>>(gamma, beta);
    final_kernel <<<dim3(64, 4, 4), 256>>>(x, out);
}

// round 15
// speedup vs baseline: 1.8835x; 1.0429x over previous
#include <cuda_runtime.h>
#include <cuda_bf16.h>
#include <math.h>
#include <stdint.h>

#define B_   4
#define C_   256
#define CI_  128
#define HW_  4096
#define MALL (B_*HW_)          // 16384
#define EPSbn 1e-5f

// ---------------- static scratch (no allocations allowed) ----------------
__device__ __nv_bfloat16 g_th[(size_t)MALL * CI_];      // theta hi [m][ci]
__device__ __nv_bfloat16 g_tl[(size_t)MALL * CI_];      // theta lo
__device__ __nv_bfloat16 g_phh[(size_t)MALL * CI_];     // phi hi
__device__ __nv_bfloat16 g_phl[(size_t)MALL * CI_];     // phi lo
__device__ __nv_bfloat16 g_gh[(size_t)MALL * CI_];      // g hi [m][ci]
__device__ __nv_bfloat16 g_gl[(size_t)MALL * CI_];      // g lo
__device__ __nv_bfloat16 g_yh[(size_t)MALL * CI_];      // y hi
__device__ __nv_bfloat16 g_yl[(size_t)MALL * CI_];      // y lo
__device__ __nv_bfloat16 g_owh[(size_t)C_ * CI_];       // out_w hi
__device__ __nv_bfloat16 g_owl[(size_t)C_ * CI_];       // out_w lo
__device__ float g_o[(size_t)MALL * C_];
__device__ float g_ps[2][128][256];                     // per-128-row-chunk stats
__device__ float g_scale[C_];
__device__ float g_shift[C_];

// ---------------- portable tensor-core helpers (sm_80+ PTX) ---------------
__device__ __forceinline__ uint32_t smem_u32(const void* p) {
    uint32_t a;
    asm("{ .reg .u64 t; cvta.to.shared.u64 t, %1; cvt.u32.u64 %0, t; }" : "=r"(a) : "l"(p));
    return a;
}
__device__ __forceinline__ void ldsm4(uint32_t* r, uint32_t addr) {
    asm volatile("ldmatrix.sync.aligned.m8n8.x4.shared.b16 {%0,%1,%2,%3}, [%4];"
        : "=r"(r[0]), "=r"(r[1]), "=r"(r[2]), "=r"(r[3]) : "r"(addr));
}
__device__ __forceinline__ void ldsm4t(uint32_t* r, uint32_t addr) {
    asm volatile("ldmatrix.sync.aligned.m8n8.x4.trans.shared.b16 {%0,%1,%2,%3}, [%4];"
        : "=r"(r[0]), "=r"(r[1]), "=r"(r[2]), "=r"(r[3]) : "r"(addr));
}
__device__ __forceinline__ void mma_bf16(float* c, const uint32_t* a, const uint32_t* b) {
    asm volatile(
        "mma.sync.aligned.m16n8k16.row.col.f32.bf16.bf16.f32 "
        "{%0,%1,%2,%3}, {%4,%5,%6,%7}, {%8,%9}, {%0,%1,%2,%3};"
        : "+f"(c[0]), "+f"(c[1]), "+f"(c[2]), "+f"(c[3])
        : "r"(a[0]), "r"(a[1]), "r"(a[2]), "r"(a[3]), "r"(b[0]), "r"(b[1]));
}
__device__ __forceinline__ void split1(float v, __nv_bfloat16& h, __nv_bfloat16& l) {
    h = __float2bfloat16(v);
    l = __float2bfloat16(v - __bfloat162float(h));
}
__device__ __forceinline__ uint32_t pack2(__nv_bfloat16 a, __nv_bfloat16 b) {
    __nv_bfloat162 v; v.x = a; v.y = b;
    return *(uint32_t*)&v;
}
__device__ __forceinline__ void cpa16(uint32_t dst, const void* src) {
    asm volatile("cp.async.cg.shared.global [%0], [%1], 16;" :: "r"(dst), "l"(src));
}
#define CP_COMMIT() asm volatile("cp.async.commit_group;" ::: "memory")
#define CP_WAIT0()  asm volatile("cp.async.wait_group 0;" ::: "memory")

// ---------------- kernel 1: projections (128x128x8 dbuf SGEMM) ------------
// grid (3 n-seg, 128 m), block 256, 2 CTA/SM.
// A[m][k] = x[b][k][s] (K-major source), B[n][k] = W[n][k]; epilogue splits
// to bf16 hi/lo planes with bias. k-order sequential -> bitwise == old proj.
__global__ __launch_bounds__(256, 2)
void proj_kernel(const float* __restrict__ x,
                 const float* __restrict__ gw,  const float* __restrict__ gb,
                 const float* __restrict__ tw,  const float* __restrict__ tb,
                 const float* __restrict__ pw,  const float* __restrict__ pb) {
    __shared__ float As[2][8][132];
    __shared__ float Bs[2][8][132];
    const int t  = threadIdx.x;
    const int n0 = blockIdx.x * 128;           // 0 / 128 / 256
    const int m0 = blockIdx.y * 128;
    const int b  = m0 / HW_;
    const int s0 = m0 % HW_;
    const int seg = n0 >> 7;

    const float* wbase = (seg == 0) ? gw : ((seg == 1) ? tw : pw);
    const float* bbase = (seg == 0) ? gb : ((seg == 1) ? tb : pb);
    const float* xb = x + (size_t)b * C_ * HW_;

    const int a_kk = t >> 5, a_m4 = (t & 31) * 4;   // A: 8 k-rows x 128 m
    const int b_nn = t >> 1, b_k4 = (t & 1) * 4;    // B: 128 n-rows x 8 k
    const int tx = t & 15, ty = t >> 4;

    float acc[8][8];
    #pragma unroll
    for (int i = 0; i < 8; i++)
        #pragma unroll
        for (int j = 0; j < 8; j++) acc[i][j] = 0.f;

    auto st = [&](int buf, float4 a, float4 bv) {
        As[buf][a_kk][a_m4+0] = a.x; As[buf][a_kk][a_m4+1] = a.y;
        As[buf][a_kk][a_m4+2] = a.z; As[buf][a_kk][a_m4+3] = a.w;
        Bs[buf][b_k4+0][b_nn] = bv.x; Bs[buf][b_k4+1][b_nn] = bv.y;
        Bs[buf][b_k4+2][b_nn] = bv.z; Bs[buf][b_k4+3][b_nn] = bv.w;
    };

    const int nit = C_ >> 3;   // 32
    float4 pa  = *(const float4*)&xb[(size_t)a_kk * HW_ + s0 + a_m4];
    float4 pb2 = *(const float4*)&wbase[(size_t)b_nn * C_ + b_k4];
    st(0, pa, pb2);
    __syncthreads();

    for (int it = 0; it < nit; it++) {
        const int cur = it & 1;
        if (it + 1 < nit) {
            const int k0 = (it + 1) * 8;
            pa  = *(const float4*)&xb[(size_t)(k0 + a_kk) * HW_ + s0 + a_m4];
            pb2 = *(const float4*)&wbase[(size_t)b_nn * C_ + k0 + b_k4];
        }
        #pragma unroll
        for (int k = 0; k < 8; k++) {
            float a[8], bb[8];
            *(float4*)&a[0]  = *(const float4*)&As[cur][k][ty*4];
            *(float4*)&a[4]  = *(const float4*)&As[cur][k][64 + ty*4];
            *(float4*)&bb[0] = *(const float4*)&Bs[cur][k][tx*4];
            *(float4*)&bb[4] = *(const float4*)&Bs[cur][k][64 + tx*4];
            #pragma unroll
            for (int i = 0; i < 8; i++)
                #pragma unroll
                for (int j = 0; j < 8; j++) acc[i][j] += a[i] * bb[j];
        }
        if (it + 1 < nit) st(cur^1, pa, pb2);
        __syncthreads();
    }

    __nv_bfloat16* ph = (seg == 0) ? g_gh : ((seg == 1) ? g_th : g_phh);
    __nv_bfloat16* pl = (seg == 0) ? g_gl : ((seg == 1) ? g_tl : g_phl);
    #pragma unroll
    for (int i = 0; i < 8; i++) {
        const int gm = m0 + ((i < 4) ? (ty*4 + i) : (64 + ty*4 + i - 4));
        #pragma unroll
        for (int half = 0; half < 2; half++) {
            const int c0 = half * 64 + tx*4;   // column within segment
            union { __nv_bfloat16 h[4]; uint2 u; } H;
            union { __nv_bfloat16 l[4]; uint2 u; } L;
            #pragma unroll
            for (int jj = 0; jj < 4; jj++)
                split1(acc[i][half*4 + jj] + bbase[c0 + jj], H.h[jj], L.l[jj]);
            *(uint2*)&ph[(size_t)gm * CI_ + c0] = H.u;
            *(uint2*)&pl[(size_t)gm * CI_ + c0] = L.u;
        }
    }
}

// ---------------- kernel 1b: out_w -> bf16 hi/lo --------------------------
__global__ void wconv_kernel(const float* __restrict__ ow) {
    const int i = blockIdx.x * 256 + threadIdx.x;   // 0..32767
    split1(ow[i], g_owh[i], g_owl[i]);
}

// ---------------- kernel 2: fused flash attention, pipelined frags --------
#define ATT_SMEM 104448
__global__ __launch_bounds__(128, 2) void attn_fused() {
    extern __shared__ char sm[];
    const int t = threadIdx.x, w = t >> 5, l = t & 31;
    const int m0 = blockIdx.x * 64;
    const int b  = blockIdx.y;

    char* TH = sm;
    char* TL = sm + 17408;

    const size_t thbase = ((size_t)b * HW_ + m0) * CI_;
    const __nv_bfloat16* PhiH = g_phh + (size_t)b * HW_ * CI_;
    const __nv_bfloat16* PhiL = g_phl + (size_t)b * HW_ * CI_;
    const __nv_bfloat16* GHp  = g_gh  + (size_t)b * HW_ * CI_;
    const __nv_bfloat16* GLp  = g_gl  + (size_t)b * HW_ * CI_;

    for (int i = t; i < 1024; i += 128) {
        const int row = i >> 4, c16 = i & 15;
        cpa16(smem_u32(TH + row*272 + c16*16), g_th + thbase + (size_t)row*CI_ + c16*8);
        cpa16(smem_u32(TL + row*272 + c16*16), g_tl + thbase + (size_t)row*CI_ + c16*8);
    }

    auto load_chunk = [&](int buf, int n0) {
        char* base = sm + 34816 + buf * 34816;
        for (int i = t; i < 512; i += 128) {
            const int row = i >> 4, c16 = i & 15;
            const size_t so = (size_t)(n0 + row) * CI_ + c16 * 8;
            const int dof = row*272 + c16*16;
            cpa16(smem_u32(base +         dof), PhiH + so);
            cpa16(smem_u32(base +  8704 + dof), PhiL + so);
            cpa16(smem_u32(base + 17408 + dof), GHp + so);
            cpa16(smem_u32(base + 26112 + dof), GLp + so);
        }
    };

    load_chunk(0, 0);
    CP_COMMIT();

    const int wm = w * 16;

    const int a_row = (l & 7) + ((l >> 3) & 1) * 8;
    const int a_kb  = (l >> 4) * 8;
    const int b_row = (l & 7) + (l >> 4) * 8;
    const int b_kb  = ((l >> 3) & 1) * 8;
    const int y_row = (l & 7) + ((l >> 3) & 1) * 8;
    const int y_cb  = (l >> 4) * 8;
    const int qr = l >> 2, qc = (l & 3) * 2;

    float Y[16][4];
    #pragma unroll
    for (int i = 0; i < 16; i++)
        #pragma unroll
        for (int j = 0; j < 4; j++) Y[i][j] = 0.f;
    float rs0 = 0.f, rs1 = 0.f;

    for (int c = 0; c < 128; c++) {
        const int cur = c & 1;
        CP_WAIT0();
        __syncthreads();
        if (c + 1 < 128) { load_chunk(cur ^ 1, (c + 1) * 32); CP_COMMIT(); }

        char* FH = sm + 34816 + cur * 34816;
        char* FL = FH + 8704;
        char* GS = FH + 17408;
        char* GSL = FH + 26112;

        // ---- S = theta . phi^T (pipelined fragment double-buffer) ----
        float S[4][4];
        #pragma unroll
        for (int i = 0; i < 4; i++)
            #pragma unroll
            for (int j = 0; j < 4; j++) S[i][j] = 0.f;

        uint32_t aHp[2][4], aLp[2][4], bHp[2][4][2], bLp[2][4][2];
        auto loadSfrag = [&](int ks, int pb) {
            const int aoff = (wm + a_row) * 272 + (ks*16 + a_kb) * 2;
            ldsm4(aHp[pb], smem_u32(TH + aoff));
            ldsm4(aLp[pb], smem_u32(TL + aoff));
            #pragma unroll
            for (int q = 0; q < 2; q++) {
                const int boff = (q*16 + b_row) * 272 + (ks*16 + b_kb) * 2;
                uint32_t r[4];
                ldsm4(r, smem_u32(FH + boff));
                bHp[pb][2*q][0] = r[0]; bHp[pb][2*q][1] = r[1];
                bHp[pb][2*q+1][0] = r[2]; bHp[pb][2*q+1][1] = r[3];
                ldsm4(r, smem_u32(FL + boff));
                bLp[pb][2*q][0] = r[0]; bLp[pb][2*q][1] = r[1];
                bLp[pb][2*q+1][0] = r[2]; bLp[pb][2*q+1][1] = r[3];
            }
        };

        loadSfrag(0, 0);
        #pragma unroll
        for (int ks = 0; ks < 8; ks++) {
            const int pb = ks & 1;
            if (ks + 1 < 8) loadSfrag(ks + 1, pb ^ 1);
            #pragma unroll
            for (int nf = 0; nf < 4; nf++) mma_bf16(S[nf], aHp[pb], bHp[pb][nf]);
            #pragma unroll
            for (int nf = 0; nf < 4; nf++) mma_bf16(S[nf], aHp[pb], bLp[pb][nf]);
            #pragma unroll
            for (int nf = 0; nf < 4; nf++) mma_bf16(S[nf], aLp[pb], bHp[pb][nf]);
        }

        // ---- exp(s-20) in regs + rowsum ----
        #pragma unroll
        for (int nf = 0; nf < 4; nf++) {
            S[nf][0] = __expf(S[nf][0] - 20.0f);
            S[nf][1] = __expf(S[nf][1] - 20.0f);
            S[nf][2] = __expf(S[nf][2] - 20.0f);
            S[nf][3] = __expf(S[nf][3] - 20.0f);
            rs0 += S[nf][0] + S[nf][1];
            rs1 += S[nf][2] + S[nf][3];
        }

        // ---- build both ks A-frags up front ----
        uint32_t aHY[2][4], aLY[2][4];
        #pragma unroll
        for (int ks = 0; ks < 2; ks++) {
            __nv_bfloat16 h0,l0,h1,l1;
            const float* s0 = S[2*ks];
            const float* s1 = S[2*ks+1];
            split1(s0[0], h0, l0); split1(s0[1], h1, l1);
            aHY[ks][0] = pack2(h0, h1); aLY[ks][0] = pack2(l0, l1);
            split1(s0[2], h0, l0); split1(s0[3], h1, l1);
            aHY[ks][1] = pack2(h0, h1); aLY[ks][1] = pack2(l0, l1);
            split1(s1[0], h0, l0); split1(s1[1], h1, l1);
            aHY[ks][2] = pack2(h0, h1); aLY[ks][2] = pack2(l0, l1);
            split1(s1[2], h0, l0); split1(s1[3], h1, l1);
            aHY[ks][3] = pack2(h0, h1); aLY[ks][3] = pack2(l0, l1);
        }

        // ---- Y += P . g  (pipelined B-fragment double-buffer) ----
        uint32_t bhY[2][4][2], blY[2][4][2];
        auto loadYfrag = [&](int it, int pb) {
            const int ks = it >> 2, qp = it & 3;
            const int off0 = (ks*16 + y_row) * 272 + ((2*qp)*16 + y_cb) * 2;
            uint32_t rh0[4], rl0[4], rh1[4], rl1[4];
            ldsm4t(rh0, smem_u32(GS  + off0));
            ldsm4t(rl0, smem_u32(GSL + off0));
            ldsm4t(rh1, smem_u32(GS  + off0 + 32));
            ldsm4t(rl1, smem_u32(GSL + off0 + 32));
            bhY[pb][0][0] = rh0[0]; bhY[pb][0][1] = rh0[1];
            bhY[pb][1][0] = rh0[2]; bhY[pb][1][1] = rh0[3];
            bhY[pb][2][0] = rh1[0]; bhY[pb][2][1] = rh1[1];
            bhY[pb][3][0] = rh1[2]; bhY[pb][3][1] = rh1[3];
            blY[pb][0][0] = rl0[0]; blY[pb][0][1] = rl0[1];
            blY[pb][1][0] = rl0[2]; blY[pb][1][1] = rl0[3];
            blY[pb][2][0] = rl1[0]; blY[pb][2][1] = rl1[1];
            blY[pb][3][0] = rl1[2]; blY[pb][3][1] = rl1[3];
        };

        loadYfrag(0, 0);
        #pragma unroll
        for (int it = 0; it < 8; it++) {
            const int pb = it & 1;
            if (it + 1 < 8) loadYfrag(it + 1, pb ^ 1);
            const int ks = it >> 2, qp = it & 3;
            float* ya = Y[4*qp];
            #pragma unroll
            for (int i = 0; i < 4; i++) mma_bf16(&ya[4*i], aHY[ks], bhY[pb][i]);
            #pragma unroll
            for (int i = 0; i < 4; i++) mma_bf16(&ya[4*i], aHY[ks], blY[pb][i]);
            #pragma unroll
            for (int i = 0; i < 4; i++) mma_bf16(&ya[4*i], aLY[ks], bhY[pb][i]);
        }
    }

    // ---- epilogue: quad rowsum reduce, normalize, bf16 hi/lo y ----
    rs0 += __shfl_xor_sync(0xffffffffu, rs0, 1);
    rs0 += __shfl_xor_sync(0xffffffffu, rs0, 2);
    rs1 += __shfl_xor_sync(0xffffffffu, rs1, 1);
    rs1 += __shfl_xor_sync(0xffffffffu, rs1, 2);
    const float ri0 = 1.0f / rs0;
    const float ri1 = 1.0f / rs1;

    const size_t yb = (size_t)b * HW_ + m0;
    const int r0 = wm + qr, r1 = r0 + 8;
    #pragma unroll
    for (int nf = 0; nf < 16; nf++) {
        const int col = nf*8 + qc;
        float v00 = Y[nf][0] * ri0, v01 = Y[nf][1] * ri0;
        float v10 = Y[nf][2] * ri1, v11 = Y[nf][3] * ri1;
        __nv_bfloat16 h0,l0,h1,l1;
        split1(v00, h0, l0); split1(v01, h1, l1);
        *(uint32_t*)&g_yh[(yb + r0) * CI_ + col] = pack2(h0, h1);
        *(uint32_t*)&g_yl[(yb + r0) * CI_ + col] = pack2(l0, l1);
        split1(v10, h0, l0); split1(v11, h1, l1);
        *(uint32_t*)&g_yh[(yb + r1) * CI_ + col] = pack2(h0, h1);
        *(uint32_t*)&g_yl[(yb + r1) * CI_ + col] = pack2(l0, l1);
    }
}

// ---------------- kernel 3: out conv via mma + fused BN partial stats -----
#define OC_PITCH 272
#define OC_PLANE (128 * OC_PITCH)   // 34816
__global__ __launch_bounds__(256, 1) void outconv_mma(const float* __restrict__ bias) {
    extern __shared__ char dsm[];
    const int t  = threadIdx.x;
    const int w  = t >> 5;
    const int l  = t & 31;
    const int m0 = blockIdx.y * 128;
    const int n0 = blockIdx.x * 128;

    char* Ah = dsm;
    char* Al = dsm + OC_PLANE;
    char* Bh = dsm + 2 * OC_PLANE;
    char* Bl = dsm + 3 * OC_PLANE;

    {
        const size_t ar = (size_t)m0 * CI_;
        const size_t br = (size_t)n0 * CI_;
        for (int i = t; i < 2048; i += 256) {
            const int row = i >> 4, c = i & 15;
            const size_t so = (size_t)row * CI_ + c * 8;
            const int dof = row * OC_PITCH + c * 16;
            cpa16(smem_u32(Ah + dof), g_yh  + ar + so);
            cpa16(smem_u32(Al + dof), g_yl  + ar + so);
            cpa16(smem_u32(Bh + dof), g_owh + br + so);
            cpa16(smem_u32(Bl + dof), g_owl + br + so);
        }
    }
    CP_COMMIT(); CP_WAIT0();
    __syncthreads();

    const int wm = (w >> 1) * 32;
    const int wn = (w & 1) * 64;

    float acc[2][8][4];
    #pragma unroll
    for (int i = 0; i < 2; i++)
        #pragma unroll
        for (int j = 0; j < 8; j++)
            #pragma unroll
            for (int k = 0; k < 4; k++) acc[i][j][k] = 0.f;

    const int a_row = (l & 7) + ((l >> 3) & 1) * 8;
    const int a_kb  = (l >> 4) * 8;
    const int b_row = (l & 7) + (l >> 4) * 8;
    const int b_kb  = ((l >> 3) & 1) * 8;

    #pragma unroll
    for (int ks = 0; ks < 8; ks++) {
        uint32_t aH[2][4], aL[2][4];
        #pragma unroll
        for (int mf = 0; mf < 2; mf++) {
            const int off = (wm + mf*16 + a_row) * OC_PITCH + (ks*16 + a_kb) * 2;
            ldsm4(aH[mf], smem_u32(Ah + off));
            ldsm4(aL[mf], smem_u32(Al + off));
        }
        uint32_t bH[8][2], bL[8][2];
        #pragma unroll
        for (int q = 0; q < 4; q++) {
            const int off = (wn + q*16 + b_row) * OC_PITCH + (ks*16 + b_kb) * 2;
            uint32_t r[4];
            ldsm4(r, smem_u32(Bh + off));
            bH[2*q][0] = r[0]; bH[2*q][1] = r[1]; bH[2*q+1][0] = r[2]; bH[2*q+1][1] = r[3];
            ldsm4(r, smem_u32(Bl + off));
            bL[2*q][0] = r[0]; bL[2*q][1] = r[1]; bL[2*q+1][0] = r[2]; bL[2*q+1][1] = r[3];
        }
        #pragma unroll
        for (int mf = 0; mf < 2; mf++)
            #pragma unroll
            for (int nf = 0; nf < 8; nf++) mma_bf16(acc[mf][nf], aH[mf], bH[nf]);
        #pragma unroll
        for (int mf = 0; mf < 2; mf++)
            #pragma unroll
            for (int nf = 0; nf < 8; nf++) mma_bf16(acc[mf][nf], aH[mf], bL[nf]);
        #pragma unroll
        for (int mf = 0; mf < 2; mf++)
            #pragma unroll
            for (int nf = 0; nf < 8; nf++) mma_bf16(acc[mf][nf], aL[mf], bH[nf]);
    }

    // add bias, store o, accumulate per-col partial sums/sumsq
    const int qr = l >> 2, qc = (l & 3) * 2;
    float cs[16], cq[16];
    #pragma unroll
    for (int i = 0; i < 16; i++) { cs[i] = 0.f; cq[i] = 0.f; }

    #pragma unroll
    for (int mf = 0; mf < 2; mf++) {
        const int r0 = m0 + wm + mf*16 + qr;
        const int r1 = r0 + 8;
        #pragma unroll
        for (int nf = 0; nf < 8; nf++) {
            const int col = n0 + wn + nf*8 + qc;
            const float b0 = bias[col], b1 = bias[col+1];
            float v0 = acc[mf][nf][0] + b0, v1 = acc[mf][nf][1] + b1;
            float v2 = acc[mf][nf][2] + b0, v3 = acc[mf][nf][3] + b1;
            *(float2*)&g_o[(size_t)r0 * C_ + col] = make_float2(v0, v1);
            *(float2*)&g_o[(size_t)r1 * C_ + col] = make_float2(v2, v3);
            cs[2*nf]   += v0 + v2;  cq[2*nf]   += v0*v0 + v2*v2;
            cs[2*nf+1] += v1 + v3;  cq[2*nf+1] += v1*v1 + v3*v3;
        }
    }
    #pragma unroll
    for (int i = 0; i < 16; i++) {
        #pragma unroll
        for (int o = 4; o < 32; o <<= 1) {
            cs[i] += __shfl_xor_sync(0xffffffffu, cs[i], o);
            cq[i] += __shfl_xor_sync(0xffffffffu, cq[i], o);
        }
    }
    __syncthreads();
    float* red = (float*)dsm;   // [4 mwarp][2 stat][128 col]
    if (l < 4) {
        const int mw = w >> 1;
        #pragma unroll
        for (int nf = 0; nf < 8; nf++) {
            const int colL = wn + nf*8 + l*2;
            red[(mw*2 + 0)*128 + colL]     = cs[2*nf];
            red[(mw*2 + 0)*128 + colL + 1] = cs[2*nf+1];
            red[(mw*2 + 1)*128 + colL]     = cq[2*nf];
            red[(mw*2 + 1)*128 + colL + 1] = cq[2*nf+1];
        }
    }
    __syncthreads();
    {
        const int colL = t & 127;
        const int stat = t >> 7;
        float v = red[(0*2 + stat)*128 + colL] + red[(1*2 + stat)*128 + colL]
                + red[(2*2 + stat)*128 + colL] + red[(3*2 + stat)*128 + colL];
        g_ps[stat][blockIdx.y][n0 + colL] = v;
    }
}

// ---------------- BN stats finalize ---------------------------------------
__global__ void stats2_kernel(const float* __restrict__ gamma,
                              const float* __restrict__ beta) {
    const int c = threadIdx.x;
    float s = 0.f, ss = 0.f;
    for (int k = 0; k < 128; k++) { s += g_ps[0][k][c]; ss += g_ps[1][k][c]; }
    const float inv_n = 1.0f / (float)MALL;
    float mean = s * inv_n;
    float var  = ss * inv_n - mean * mean;
    float sc = gamma[c] * rsqrtf(var + EPSbn);
    g_scale[c] = sc;
    g_shift[c] = beta[c] - mean * sc;
}

// ---------------- BN apply + ReLU + residual (x prefetched) ---------------
__global__ void final_kernel(const float* __restrict__ x, float* __restrict__ out) {
    __shared__ float tile[64][65];
    const int s0 = blockIdx.x * 64;
    const int c0 = blockIdx.y * 64;
    const int b  = blockIdx.z;
    const int t  = threadIdx.x;

    const int cl = t >> 2, sg = (t & 3) * 16;
    const int c = c0 + cl;
    const size_t base = ((size_t)b * C_ + c) * HW_ + s0 + sg;
    float4 xv[4];
    #pragma unroll
    for (int q = 0; q < 4; q++) xv[q] = *(const float4*)&x[base + q*4];

    const int lr = t >> 2, lc = (t & 3) * 16;
    #pragma unroll
    for (int q = 0; q < 4; q++) {
        float4 v = *(const float4*)&g_o[(size_t)(b*HW_ + s0 + lr) * C_ + c0 + lc + q*4];
        tile[lr][lc + q*4 + 0] = v.x; tile[lr][lc + q*4 + 1] = v.y;
        tile[lr][lc + q*4 + 2] = v.z; tile[lr][lc + q*4 + 3] = v.w;
    }
    __syncthreads();

    const float sc = g_scale[c], sh = g_shift[c];
    #pragma unroll
    for (int q = 0; q < 4; q++) {
        float4 w;
        w.x = fmaxf(tile[sg + q*4 + 0][cl] * sc + sh, 0.f) + xv[q].x;
        w.y = fmaxf(tile[sg + q*4 + 1][cl] * sc + sh, 0.f) + xv[q].y;
        w.z = fmaxf(tile[sg + q*4 + 2][cl] * sc + sh, 0.f) + xv[q].z;
        w.w = fmaxf(tile[sg + q*4 + 3][cl] * sc + sh, 0.f) + xv[q].w;
        *(float4*)&out[base + q*4] = w;
    }
}

// ---------------- launch: serial single stream ----------------------------
extern "C" void kernel_launch(void* const* d_in, const int* in_sizes, int n_in,
                              void* d_out, int out_size) {
    const float* x     = (const float*)d_in[0];
    const float* gw    = (const float*)d_in[1];
    const float* gb    = (const float*)d_in[2];
    const float* tw    = (const float*)d_in[3];
    const float* tb    = (const float*)d_in[4];
    const float* pw    = (const float*)d_in[5];
    const float* pb    = (const float*)d_in[6];
    const float* ow    = (const float*)d_in[7];
    const float* ob    = (const float*)d_in[8];
    const float* gamma = (const float*)d_in[9];
    const float* beta  = (const float*)d_in[10];
    float* out = (float*)d_out;

    cudaFuncSetAttribute(attn_fused,  cudaFuncAttributeMaxDynamicSharedMemorySize, ATT_SMEM);
    cudaFuncSetAttribute(outconv_mma, cudaFuncAttributeMaxDynamicSharedMemorySize, 4 * OC_PLANE);

    wconv_kernel <<<dim3(128),      256>>>(ow);
    proj_kernel  <<<dim3(3, 128),   256>>>(x, gw, gb, tw, tb, pw, pb);
    attn_fused   <<<dim3(64, 4),    128, ATT_SMEM>>>();
    outconv_mma  <<<dim3(2, 128),   256, 4 * OC_PLANE>>>(ob);
    stats2_kernel<<<dim3(1),        256>>>(gamma, beta);
    final_kernel <<<dim3(64, 4, 4), 256>>>(x, out);
}

// round 16
// speedup vs baseline: 2.0632x; 1.0954x over previous
#include <cuda_runtime.h>
#include <cuda_bf16.h>
#include <math.h>
#include <stdint.h>

#define B_   4
#define C_   256
#define CI_  128
#define HW_  4096
#define MALL (B_*HW_)          // 16384
#define NKQ  4                 // key-range split factor
#define KQL  (HW_/NKQ)         // 1024 keys per job
#define EPSbn 1e-5f

// ---------------- static scratch (no allocations allowed) ----------------
__device__ __nv_bfloat16 g_th[(size_t)MALL * CI_];      // theta hi [m][ci]
__device__ __nv_bfloat16 g_tl[(size_t)MALL * CI_];      // theta lo
__device__ __nv_bfloat16 g_phh[(size_t)MALL * CI_];     // phi hi
__device__ __nv_bfloat16 g_phl[(size_t)MALL * CI_];     // phi lo
__device__ __nv_bfloat16 g_gh[(size_t)MALL * CI_];      // g hi [m][ci]
__device__ __nv_bfloat16 g_gl[(size_t)MALL * CI_];      // g lo
__device__ __nv_bfloat16 g_yh[(size_t)MALL * CI_];      // y hi
__device__ __nv_bfloat16 g_yl[(size_t)MALL * CI_];      // y lo
__device__ __nv_bfloat16 g_owh[(size_t)C_ * CI_];       // out_w hi
__device__ __nv_bfloat16 g_owl[(size_t)C_ * CI_];       // out_w lo
__device__ float g_part[(size_t)MALL * NKQ * CI_];      // split-K Y partials, 33.5MB
__device__ float g_rsum[(size_t)MALL * NKQ];            // split rowsum partials
__device__ float g_o[(size_t)MALL * C_];
__device__ float g_ps[2][128][256];                     // per-128-row-chunk stats
__device__ float g_scale[C_];
__device__ float g_shift[C_];

// ---------------- portable tensor-core helpers (sm_80+ PTX) ---------------
__device__ __forceinline__ uint32_t smem_u32(const void* p) {
    uint32_t a;
    asm("{ .reg .u64 t; cvta.to.shared.u64 t, %1; cvt.u32.u64 %0, t; }" : "=r"(a) : "l"(p));
    return a;
}
__device__ __forceinline__ void ldsm4(uint32_t* r, uint32_t addr) {
    asm volatile("ldmatrix.sync.aligned.m8n8.x4.shared.b16 {%0,%1,%2,%3}, [%4];"
        : "=r"(r[0]), "=r"(r[1]), "=r"(r[2]), "=r"(r[3]) : "r"(addr));
}
__device__ __forceinline__ void ldsm4t(uint32_t* r, uint32_t addr) {
    asm volatile("ldmatrix.sync.aligned.m8n8.x4.trans.shared.b16 {%0,%1,%2,%3}, [%4];"
        : "=r"(r[0]), "=r"(r[1]), "=r"(r[2]), "=r"(r[3]) : "r"(addr));
}
__device__ __forceinline__ void mma_bf16(float* c, const uint32_t* a, const uint32_t* b) {
    asm volatile(
        "mma.sync.aligned.m16n8k16.row.col.f32.bf16.bf16.f32 "
        "{%0,%1,%2,%3}, {%4,%5,%6,%7}, {%8,%9}, {%0,%1,%2,%3};"
        : "+f"(c[0]), "+f"(c[1]), "+f"(c[2]), "+f"(c[3])
        : "r"(a[0]), "r"(a[1]), "r"(a[2]), "r"(a[3]), "r"(b[0]), "r"(b[1]));
}
__device__ __forceinline__ void split1(float v, __nv_bfloat16& h, __nv_bfloat16& l) {
    h = __float2bfloat16(v);
    l = __float2bfloat16(v - __bfloat162float(h));
}
__device__ __forceinline__ uint32_t pack2(__nv_bfloat16 a, __nv_bfloat16 b) {
    __nv_bfloat162 v; v.x = a; v.y = b;
    return *(uint32_t*)&v;
}
__device__ __forceinline__ void cpa16(uint32_t dst, const void* src) {
    asm volatile("cp.async.cg.shared.global [%0], [%1], 16;" :: "r"(dst), "l"(src));
}
#define CP_COMMIT() asm volatile("cp.async.commit_group;" ::: "memory")
#define CP_WAIT0()  asm volatile("cp.async.wait_group 0;" ::: "memory")

// ---------------- kernel 1: projections (128x128x8 dbuf SGEMM) ------------
__global__ __launch_bounds__(256, 2)
void proj_kernel(const float* __restrict__ x,
                 const float* __restrict__ gw,  const float* __restrict__ gb,
                 const float* __restrict__ tw,  const float* __restrict__ tb,
                 const float* __restrict__ pw,  const float* __restrict__ pb) {
    __shared__ float As[2][8][132];
    __shared__ float Bs[2][8][132];
    const int t  = threadIdx.x;
    const int n0 = blockIdx.x * 128;           // 0 / 128 / 256
    const int m0 = blockIdx.y * 128;
    const int b  = m0 / HW_;
    const int s0 = m0 % HW_;
    const int seg = n0 >> 7;

    const float* wbase = (seg == 0) ? gw : ((seg == 1) ? tw : pw);
    const float* bbase = (seg == 0) ? gb : ((seg == 1) ? tb : pb);
    const float* xb = x + (size_t)b * C_ * HW_;

    const int a_kk = t >> 5, a_m4 = (t & 31) * 4;
    const int b_nn = t >> 1, b_k4 = (t & 1) * 4;
    const int tx = t & 15, ty = t >> 4;

    float acc[8][8];
    #pragma unroll
    for (int i = 0; i < 8; i++)
        #pragma unroll
        for (int j = 0; j < 8; j++) acc[i][j] = 0.f;

    auto st = [&](int buf, float4 a, float4 bv) {
        As[buf][a_kk][a_m4+0] = a.x; As[buf][a_kk][a_m4+1] = a.y;
        As[buf][a_kk][a_m4+2] = a.z; As[buf][a_kk][a_m4+3] = a.w;
        Bs[buf][b_k4+0][b_nn] = bv.x; Bs[buf][b_k4+1][b_nn] = bv.y;
        Bs[buf][b_k4+2][b_nn] = bv.z; Bs[buf][b_k4+3][b_nn] = bv.w;
    };

    const int nit = C_ >> 3;   // 32
    float4 pa  = *(const float4*)&xb[(size_t)a_kk * HW_ + s0 + a_m4];
    float4 pb2 = *(const float4*)&wbase[(size_t)b_nn * C_ + b_k4];
    st(0, pa, pb2);
    __syncthreads();

    for (int it = 0; it < nit; it++) {
        const int cur = it & 1;
        if (it + 1 < nit) {
            const int k0 = (it + 1) * 8;
            pa  = *(const float4*)&xb[(size_t)(k0 + a_kk) * HW_ + s0 + a_m4];
            pb2 = *(const float4*)&wbase[(size_t)b_nn * C_ + k0 + b_k4];
        }
        #pragma unroll
        for (int k = 0; k < 8; k++) {
            float a[8], bb[8];
            *(float4*)&a[0]  = *(const float4*)&As[cur][k][ty*4];
            *(float4*)&a[4]  = *(const float4*)&As[cur][k][64 + ty*4];
            *(float4*)&bb[0] = *(const float4*)&Bs[cur][k][tx*4];
            *(float4*)&bb[4] = *(const float4*)&Bs[cur][k][64 + tx*4];
            #pragma unroll
            for (int i = 0; i < 8; i++)
                #pragma unroll
                for (int j = 0; j < 8; j++) acc[i][j] += a[i] * bb[j];
        }
        if (it + 1 < nit) st(cur^1, pa, pb2);
        __syncthreads();
    }

    __nv_bfloat16* ph = (seg == 0) ? g_gh : ((seg == 1) ? g_th : g_phh);
    __nv_bfloat16* pl = (seg == 0) ? g_gl : ((seg == 1) ? g_tl : g_phl);
    #pragma unroll
    for (int i = 0; i < 8; i++) {
        const int gm = m0 + ((i < 4) ? (ty*4 + i) : (64 + ty*4 + i - 4));
        #pragma unroll
        for (int half = 0; half < 2; half++) {
            const int c0 = half * 64 + tx*4;
            union { __nv_bfloat16 h[4]; uint2 u; } H;
            union { __nv_bfloat16 l[4]; uint2 u; } L;
            #pragma unroll
            for (int jj = 0; jj < 4; jj++)
                split1(acc[i][half*4 + jj] + bbase[c0 + jj], H.h[jj], L.l[jj]);
            *(uint2*)&ph[(size_t)gm * CI_ + c0] = H.u;
            *(uint2*)&pl[(size_t)gm * CI_ + c0] = L.u;
        }
    }
}

// ---------------- kernel 1b: out_w -> bf16 hi/lo --------------------------
__global__ void wconv_kernel(const float* __restrict__ ow) {
    const int i = blockIdx.x * 256 + threadIdx.x;   // 0..32767
    split1(ow[i], g_owh[i], g_owl[i]);
}

// ---------------- kernel 2: flash attention, split-K x4 for balance -------
// grid (4 kq, 64 mt, 4 b) = 1024 jobs of W/4 -> per-SM work 1.75W vs 2W.
// Writes fp32 Y partials + rowsum partials; reduce kernel normalizes.
#define ATT_SMEM 104448
__global__ __launch_bounds__(128, 2) void attn_fused() {
    extern __shared__ char sm[];
    const int t = threadIdx.x, w = t >> 5, l = t & 31;
    const int kq = blockIdx.x;
    const int m0 = blockIdx.y * 64;
    const int b  = blockIdx.z;
    const int job = ((b * 64 + blockIdx.y) * NKQ) + kq;
    const size_t kb = (size_t)kq * KQL;

    char* TH = sm;
    char* TL = sm + 17408;

    const size_t thbase = ((size_t)b * HW_ + m0) * CI_;
    const __nv_bfloat16* PhiH = g_phh + ((size_t)b * HW_ + kb) * CI_;
    const __nv_bfloat16* PhiL = g_phl + ((size_t)b * HW_ + kb) * CI_;
    const __nv_bfloat16* GHp  = g_gh  + ((size_t)b * HW_ + kb) * CI_;
    const __nv_bfloat16* GLp  = g_gl  + ((size_t)b * HW_ + kb) * CI_;

    for (int i = t; i < 1024; i += 128) {
        const int row = i >> 4, c16 = i & 15;
        cpa16(smem_u32(TH + row*272 + c16*16), g_th + thbase + (size_t)row*CI_ + c16*8);
        cpa16(smem_u32(TL + row*272 + c16*16), g_tl + thbase + (size_t)row*CI_ + c16*8);
    }

    auto load_chunk = [&](int buf, int n0) {
        char* base = sm + 34816 + buf * 34816;
        for (int i = t; i < 512; i += 128) {
            const int row = i >> 4, c16 = i & 15;
            const size_t so = (size_t)(n0 + row) * CI_ + c16 * 8;
            const int dof = row*272 + c16*16;
            cpa16(smem_u32(base +         dof), PhiH + so);
            cpa16(smem_u32(base +  8704 + dof), PhiL + so);
            cpa16(smem_u32(base + 17408 + dof), GHp + so);
            cpa16(smem_u32(base + 26112 + dof), GLp + so);
        }
    };

    load_chunk(0, 0);
    CP_COMMIT();

    const int wm = w * 16;

    const int a_row = (l & 7) + ((l >> 3) & 1) * 8;
    const int a_kb  = (l >> 4) * 8;
    const int b_row = (l & 7) + (l >> 4) * 8;
    const int b_kb  = ((l >> 3) & 1) * 8;
    const int y_row = (l & 7) + ((l >> 3) & 1) * 8;
    const int y_cb  = (l >> 4) * 8;
    const int qr = l >> 2, qc = (l & 3) * 2;

    float Y[16][4];
    #pragma unroll
    for (int i = 0; i < 16; i++)
        #pragma unroll
        for (int j = 0; j < 4; j++) Y[i][j] = 0.f;
    float rs0 = 0.f, rs1 = 0.f;

    const int NC = KQL / 32;   // 32 chunks
    for (int c = 0; c < NC; c++) {
        const int cur = c & 1;
        CP_WAIT0();
        __syncthreads();
        if (c + 1 < NC) { load_chunk(cur ^ 1, (c + 1) * 32); CP_COMMIT(); }

        char* FH = sm + 34816 + cur * 34816;
        char* FL = FH + 8704;
        char* GS = FH + 17408;
        char* GSL = FH + 26112;

        // ---- S = theta . phi^T (pipelined fragment double-buffer) ----
        float S[4][4];
        #pragma unroll
        for (int i = 0; i < 4; i++)
            #pragma unroll
            for (int j = 0; j < 4; j++) S[i][j] = 0.f;

        uint32_t aHp[2][4], aLp[2][4], bHp[2][4][2], bLp[2][4][2];
        auto loadSfrag = [&](int ks, int pb) {
            const int aoff = (wm + a_row) * 272 + (ks*16 + a_kb) * 2;
            ldsm4(aHp[pb], smem_u32(TH + aoff));
            ldsm4(aLp[pb], smem_u32(TL + aoff));
            #pragma unroll
            for (int q = 0; q < 2; q++) {
                const int boff = (q*16 + b_row) * 272 + (ks*16 + b_kb) * 2;
                uint32_t r[4];
                ldsm4(r, smem_u32(FH + boff));
                bHp[pb][2*q][0] = r[0]; bHp[pb][2*q][1] = r[1];
                bHp[pb][2*q+1][0] = r[2]; bHp[pb][2*q+1][1] = r[3];
                ldsm4(r, smem_u32(FL + boff));
                bLp[pb][2*q][0] = r[0]; bLp[pb][2*q][1] = r[1];
                bLp[pb][2*q+1][0] = r[2]; bLp[pb][2*q+1][1] = r[3];
            }
        };

        loadSfrag(0, 0);
        #pragma unroll
        for (int ks = 0; ks < 8; ks++) {
            const int pb = ks & 1;
            if (ks + 1 < 8) loadSfrag(ks + 1, pb ^ 1);
            #pragma unroll
            for (int nf = 0; nf < 4; nf++) mma_bf16(S[nf], aHp[pb], bHp[pb][nf]);
            #pragma unroll
            for (int nf = 0; nf < 4; nf++) mma_bf16(S[nf], aHp[pb], bLp[pb][nf]);
            #pragma unroll
            for (int nf = 0; nf < 4; nf++) mma_bf16(S[nf], aLp[pb], bHp[pb][nf]);
        }

        // ---- exp(s-20) in regs + rowsum ----
        #pragma unroll
        for (int nf = 0; nf < 4; nf++) {
            S[nf][0] = __expf(S[nf][0] - 20.0f);
            S[nf][1] = __expf(S[nf][1] - 20.0f);
            S[nf][2] = __expf(S[nf][2] - 20.0f);
            S[nf][3] = __expf(S[nf][3] - 20.0f);
            rs0 += S[nf][0] + S[nf][1];
            rs1 += S[nf][2] + S[nf][3];
        }

        // ---- build both ks A-frags up front ----
        uint32_t aHY[2][4], aLY[2][4];
        #pragma unroll
        for (int ks = 0; ks < 2; ks++) {
            __nv_bfloat16 h0,l0,h1,l1;
            const float* s0 = S[2*ks];
            const float* s1 = S[2*ks+1];
            split1(s0[0], h0, l0); split1(s0[1], h1, l1);
            aHY[ks][0] = pack2(h0, h1); aLY[ks][0] = pack2(l0, l1);
            split1(s0[2], h0, l0); split1(s0[3], h1, l1);
            aHY[ks][1] = pack2(h0, h1); aLY[ks][1] = pack2(l0, l1);
            split1(s1[0], h0, l0); split1(s1[1], h1, l1);
            aHY[ks][2] = pack2(h0, h1); aLY[ks][2] = pack2(l0, l1);
            split1(s1[2], h0, l0); split1(s1[3], h1, l1);
            aHY[ks][3] = pack2(h0, h1); aLY[ks][3] = pack2(l0, l1);
        }

        // ---- Y += P . g  (pipelined B-fragment double-buffer) ----
        uint32_t bhY[2][4][2], blY[2][4][2];
        auto loadYfrag = [&](int it, int pb) {
            const int ks = it >> 2, qp = it & 3;
            const int off0 = (ks*16 + y_row) * 272 + ((2*qp)*16 + y_cb) * 2;
            uint32_t rh0[4], rl0[4], rh1[4], rl1[4];
            ldsm4t(rh0, smem_u32(GS  + off0));
            ldsm4t(rl0, smem_u32(GSL + off0));
            ldsm4t(rh1, smem_u32(GS  + off0 + 32));
            ldsm4t(rl1, smem_u32(GSL + off0 + 32));
            bhY[pb][0][0] = rh0[0]; bhY[pb][0][1] = rh0[1];
            bhY[pb][1][0] = rh0[2]; bhY[pb][1][1] = rh0[3];
            bhY[pb][2][0] = rh1[0]; bhY[pb][2][1] = rh1[1];
            bhY[pb][3][0] = rh1[2]; bhY[pb][3][1] = rh1[3];
            blY[pb][0][0] = rl0[0]; blY[pb][0][1] = rl0[1];
            blY[pb][1][0] = rl0[2]; blY[pb][1][1] = rl0[3];
            blY[pb][2][0] = rl1[0]; blY[pb][2][1] = rl1[1];
            blY[pb][3][0] = rl1[2]; blY[pb][3][1] = rl1[3];
        };

        loadYfrag(0, 0);
        #pragma unroll
        for (int it = 0; it < 8; it++) {
            const int pb = it & 1;
            if (it + 1 < 8) loadYfrag(it + 1, pb ^ 1);
            const int ks = it >> 2, qp = it & 3;
            float* ya = Y[4*qp];
            #pragma unroll
            for (int i = 0; i < 4; i++) mma_bf16(&ya[4*i], aHY[ks], bhY[pb][i]);
            #pragma unroll
            for (int i = 0; i < 4; i++) mma_bf16(&ya[4*i], aHY[ks], blY[pb][i]);
            #pragma unroll
            for (int i = 0; i < 4; i++) mma_bf16(&ya[4*i], aLY[ks], bhY[pb][i]);
        }
    }

    // ---- epilogue: rowsum partials + fp32 Y partials ----
    rs0 += __shfl_xor_sync(0xffffffffu, rs0, 1);
    rs0 += __shfl_xor_sync(0xffffffffu, rs0, 2);
    rs1 += __shfl_xor_sync(0xffffffffu, rs1, 1);
    rs1 += __shfl_xor_sync(0xffffffffu, rs1, 2);
    if ((l & 3) == 0) {
        g_rsum[(size_t)job * 64 + wm + qr]     = rs0;
        g_rsum[(size_t)job * 64 + wm + qr + 8] = rs1;
    }

    float* P0 = g_part + (size_t)job * 64 * CI_;
    const int r0 = wm + qr, r1 = r0 + 8;
    #pragma unroll
    for (int nf = 0; nf < 16; nf++) {
        const int col = nf*8 + qc;
        *(float2*)&P0[(size_t)r0 * CI_ + col] = make_float2(Y[nf][0], Y[nf][1]);
        *(float2*)&P0[(size_t)r1 * CI_ + col] = make_float2(Y[nf][2], Y[nf][3]);
    }
}

// ---------------- kernel 2b: split-K reduce + normalize -> bf16 y ---------
__global__ void avreduce_kernel() {
    const size_t idx = (size_t)blockIdx.x * 256 + threadIdx.x;  // float4 units
    const size_t e0 = idx * 4;
    const int m = (int)(e0 / CI_);            // global row 0..16383
    const int rt = m >> 6;                    // tile index = job base / NKQ
    const int rl = m & 63;
    const size_t pbase = (((size_t)rt * NKQ) * 64 + rl) * CI_ + (e0 % CI_);
    const size_t pstr  = (size_t)64 * CI_;

    float rs = g_rsum[((size_t)rt * NKQ + 0) * 64 + rl]
             + g_rsum[((size_t)rt * NKQ + 1) * 64 + rl]
             + g_rsum[((size_t)rt * NKQ + 2) * 64 + rl]
             + g_rsum[((size_t)rt * NKQ + 3) * 64 + rl];
    const float ri = 1.0f / rs;

    float4 s = *(const float4*)&g_part[pbase];
    #pragma unroll
    for (int k = 1; k < NKQ; k++) {
        float4 v = *(const float4*)&g_part[pbase + (size_t)k * pstr];
        s.x += v.x; s.y += v.y; s.z += v.z; s.w += v.w;
    }
    s.x *= ri; s.y *= ri; s.z *= ri; s.w *= ri;

    __nv_bfloat16 h0,l0,h1,l1;
    split1(s.x, h0, l0); split1(s.y, h1, l1);
    uint32_t H0 = pack2(h0, h1), L0 = pack2(l0, l1);
    split1(s.z, h0, l0); split1(s.w, h1, l1);
    uint32_t H1 = pack2(h0, h1), L1 = pack2(l0, l1);
    *(uint2*)&g_yh[e0] = make_uint2(H0, H1);
    *(uint2*)&g_yl[e0] = make_uint2(L0, L1);
}

// ---------------- kernel 3: out conv via mma + fused BN partial stats -----
#define OC_PITCH 272
#define OC_PLANE (128 * OC_PITCH)   // 34816
__global__ __launch_bounds__(256, 1) void outconv_mma(const float* __restrict__ bias) {
    extern __shared__ char dsm[];
    const int t  = threadIdx.x;
    const int w  = t >> 5;
    const int l  = t & 31;
    const int m0 = blockIdx.y * 128;
    const int n0 = blockIdx.x * 128;

    char* Ah = dsm;
    char* Al = dsm + OC_PLANE;
    char* Bh = dsm + 2 * OC_PLANE;
    char* Bl = dsm + 3 * OC_PLANE;

    {
        const size_t ar = (size_t)m0 * CI_;
        const size_t br = (size_t)n0 * CI_;
        for (int i = t; i < 2048; i += 256) {
            const int row = i >> 4, c = i & 15;
            const size_t so = (size_t)row * CI_ + c * 8;
            const int dof = row * OC_PITCH + c * 16;
            cpa16(smem_u32(Ah + dof), g_yh  + ar + so);
            cpa16(smem_u32(Al + dof), g_yl  + ar + so);
            cpa16(smem_u32(Bh + dof), g_owh + br + so);
            cpa16(smem_u32(Bl + dof), g_owl + br + so);
        }
    }
    CP_COMMIT(); CP_WAIT0();
    __syncthreads();

    const int wm = (w >> 1) * 32;
    const int wn = (w & 1) * 64;

    float acc[2][8][4];
    #pragma unroll
    for (int i = 0; i < 2; i++)
        #pragma unroll
        for (int j = 0; j < 8; j++)
            #pragma unroll
            for (int k = 0; k < 4; k++) acc[i][j][k] = 0.f;

    const int a_row = (l & 7) + ((l >> 3) & 1) * 8;
    const int a_kb  = (l >> 4) * 8;
    const int b_row = (l & 7) + (l >> 4) * 8;
    const int b_kb  = ((l >> 3) & 1) * 8;

    #pragma unroll
    for (int ks = 0; ks < 8; ks++) {
        uint32_t aH[2][4], aL[2][4];
        #pragma unroll
        for (int mf = 0; mf < 2; mf++) {
            const int off = (wm + mf*16 + a_row) * OC_PITCH + (ks*16 + a_kb) * 2;
            ldsm4(aH[mf], smem_u32(Ah + off));
            ldsm4(aL[mf], smem_u32(Al + off));
        }
        uint32_t bH[8][2], bL[8][2];
        #pragma unroll
        for (int q = 0; q < 4; q++) {
            const int off = (wn + q*16 + b_row) * OC_PITCH + (ks*16 + b_kb) * 2;
            uint32_t r[4];
            ldsm4(r, smem_u32(Bh + off));
            bH[2*q][0] = r[0]; bH[2*q][1] = r[1]; bH[2*q+1][0] = r[2]; bH[2*q+1][1] = r[3];
            ldsm4(r, smem_u32(Bl + off));
            bL[2*q][0] = r[0]; bL[2*q][1] = r[1]; bL[2*q+1][0] = r[2]; bL[2*q+1][1] = r[3];
        }
        #pragma unroll
        for (int mf = 0; mf < 2; mf++)
            #pragma unroll
            for (int nf = 0; nf < 8; nf++) mma_bf16(acc[mf][nf], aH[mf], bH[nf]);
        #pragma unroll
        for (int mf = 0; mf < 2; mf++)
            #pragma unroll
            for (int nf = 0; nf < 8; nf++) mma_bf16(acc[mf][nf], aH[mf], bL[nf]);
        #pragma unroll
        for (int mf = 0; mf < 2; mf++)
            #pragma unroll
            for (int nf = 0; nf < 8; nf++) mma_bf16(acc[mf][nf], aL[mf], bH[nf]);
    }

    // add bias, store o, accumulate per-col partial sums/sumsq
    const int qr = l >> 2, qc = (l & 3) * 2;
    float cs[16], cq[16];
    #pragma unroll
    for (int i = 0; i < 16; i++) { cs[i] = 0.f; cq[i] = 0.f; }

    #pragma unroll
    for (int mf = 0; mf < 2; mf++) {
        const int r0 = m0 + wm + mf*16 + qr;
        const int r1 = r0 + 8;
        #pragma unroll
        for (int nf = 0; nf < 8; nf++) {
            const int col = n0 + wn + nf*8 + qc;
            const float b0 = bias[col], b1 = bias[col+1];
            float v0 = acc[mf][nf][0] + b0, v1 = acc[mf][nf][1] + b1;
            float v2 = acc[mf][nf][2] + b0, v3 = acc[mf][nf][3] + b1;
            *(float2*)&g_o[(size_t)r0 * C_ + col] = make_float2(v0, v1);
            *(float2*)&g_o[(size_t)r1 * C_ + col] = make_float2(v2, v3);
            cs[2*nf]   += v0 + v2;  cq[2*nf]   += v0*v0 + v2*v2;
            cs[2*nf+1] += v1 + v3;  cq[2*nf+1] += v1*v1 + v3*v3;
        }
    }
    #pragma unroll
    for (int i = 0; i < 16; i++) {
        #pragma unroll
        for (int o = 4; o < 32; o <<= 1) {
            cs[i] += __shfl_xor_sync(0xffffffffu, cs[i], o);
            cq[i] += __shfl_xor_sync(0xffffffffu, cq[i], o);
        }
    }
    __syncthreads();
    float* red = (float*)dsm;
    if (l < 4) {
        const int mw = w >> 1;
        #pragma unroll
        for (int nf = 0; nf < 8; nf++) {
            const int colL = wn + nf*8 + l*2;
            red[(mw*2 + 0)*128 + colL]     = cs[2*nf];
            red[(mw*2 + 0)*128 + colL + 1] = cs[2*nf+1];
            red[(mw*2 + 1)*128 + colL]     = cq[2*nf];
            red[(mw*2 + 1)*128 + colL + 1] = cq[2*nf+1];
        }
    }
    __syncthreads();
    {
        const int colL = t & 127;
        const int stat = t >> 7;
        float v = red[(0*2 + stat)*128 + colL] + red[(1*2 + stat)*128 + colL]
                + red[(2*2 + stat)*128 + colL] + red[(3*2 + stat)*128 + colL];
        g_ps[stat][blockIdx.y][n0 + colL] = v;
    }
}

// ---------------- BN stats finalize ---------------------------------------
__global__ void stats2_kernel(const float* __restrict__ gamma,
                              const float* __restrict__ beta) {
    const int c = threadIdx.x;
    float s = 0.f, ss = 0.f;
    for (int k = 0; k < 128; k++) { s += g_ps[0][k][c]; ss += g_ps[1][k][c]; }
    const float inv_n = 1.0f / (float)MALL;
    float mean = s * inv_n;
    float var  = ss * inv_n - mean * mean;
    float sc = gamma[c] * rsqrtf(var + EPSbn);
    g_scale[c] = sc;
    g_shift[c] = beta[c] - mean * sc;
}

// ---------------- BN apply + ReLU + residual (x prefetched) ---------------
__global__ void final_kernel(const float* __restrict__ x, float* __restrict__ out) {
    __shared__ float tile[64][65];
    const int s0 = blockIdx.x * 64;
    const int c0 = blockIdx.y * 64;
    const int b  = blockIdx.z;
    const int t  = threadIdx.x;

    const int cl = t >> 2, sg = (t & 3) * 16;
    const int c = c0 + cl;
    const size_t base = ((size_t)b * C_ + c) * HW_ + s0 + sg;
    float4 xv[4];
    #pragma unroll
    for (int q = 0; q < 4; q++) xv[q] = *(const float4*)&x[base + q*4];

    const int lr = t >> 2, lc = (t & 3) * 16;
    #pragma unroll
    for (int q = 0; q < 4; q++) {
        float4 v = *(const float4*)&g_o[(size_t)(b*HW_ + s0 + lr) * C_ + c0 + lc + q*4];
        tile[lr][lc + q*4 + 0] = v.x; tile[lr][lc + q*4 + 1] = v.y;
        tile[lr][lc + q*4 + 2] = v.z; tile[lr][lc + q*4 + 3] = v.w;
    }
    __syncthreads();

    const float sc = g_scale[c], sh = g_shift[c];
    #pragma unroll
    for (int q = 0; q < 4; q++) {
        float4 w;
        w.x = fmaxf(tile[sg + q*4 + 0][cl] * sc + sh, 0.f) + xv[q].x;
        w.y = fmaxf(tile[sg + q*4 + 1][cl] * sc + sh, 0.f) + xv[q].y;
        w.z = fmaxf(tile[sg + q*4 + 2][cl] * sc + sh, 0.f) + xv[q].z;
        w.w = fmaxf(tile[sg + q*4 + 3][cl] * sc + sh, 0.f) + xv[q].w;
        *(float4*)&out[base + q*4] = w;
    }
}

// ---------------- launch: serial single stream ----------------------------
extern "C" void kernel_launch(void* const* d_in, const int* in_sizes, int n_in,
                              void* d_out, int out_size) {
    const float* x     = (const float*)d_in[0];
    const float* gw    = (const float*)d_in[1];
    const float* gb    = (const float*)d_in[2];
    const float* tw    = (const float*)d_in[3];
    const float* tb    = (const float*)d_in[4];
    const float* pw    = (const float*)d_in[5];
    const float* pb    = (const float*)d_in[6];
    const float* ow    = (const float*)d_in[7];
    const float* ob    = (const float*)d_in[8];
    const float* gamma = (const float*)d_in[9];
    const float* beta  = (const float*)d_in[10];
    float* out = (float*)d_out;

    cudaFuncSetAttribute(attn_fused,  cudaFuncAttributeMaxDynamicSharedMemorySize, ATT_SMEM);
    cudaFuncSetAttribute(outconv_mma, cudaFuncAttributeMaxDynamicSharedMemorySize, 4 * OC_PLANE);

    wconv_kernel   <<<dim3(128),        256>>>(ow);
    proj_kernel    <<<dim3(3, 128),     256>>>(x, gw, gb, tw, tb, pw, pb);
    attn_fused     <<<dim3(NKQ, 64, 4), 128, ATT_SMEM>>>();
    avreduce_kernel<<<dim3(2048),       256>>>();
    outconv_mma    <<<dim3(2, 128),     256, 4 * OC_PLANE>>>(ob);
    stats2_kernel  <<<dim3(1),          256>>>(gamma, beta);
    final_kernel   <<<dim3(64, 4, 4),   256>>>(x, out);
}